// round 1
// baseline (speedup 1.0000x reference)
#include <cuda_runtime.h>
#include <math.h>

#define B  4096
#define D  1792
#define NC 3000
#define NM 7000
#define NF 13000
#define NTOT (NC + NM + NF)

#define OFF_C ((size_t)0)
#define OFF_M ((size_t)B * NC)
#define OFF_F (OFF_M + (size_t)B * NM)

// ---- device scratch (no runtime allocation allowed) ----
__device__ float g_logits[(size_t)B * NTOT];   // ~377 MB
__device__ float g_label_xyz[B * 3];
__device__ float g_part_xyz[NTOT * 3];
__device__ int   g_gp[NF];          // coarse grandparent per fine class
__device__ int   g_label_idx[3 * B];
__device__ float g_nll[3 * B];
__device__ int   g_counts[5];

// ============================================================
// Kernel 1: precompute unit vectors, grandparents, zero counters
// ============================================================
__global__ void k_init(const float* __restrict__ labels,
                       const float* __restrict__ cpart,
                       const float* __restrict__ mpart,
                       const float* __restrict__ fpart,
                       const int*   __restrict__ mparents,
                       const int*   __restrict__ fparents)
{
    int t = blockIdx.x * blockDim.x + threadIdx.x;
    const float RADF = 0.017453292519943295f;
    if (t < B) {
        float la = labels[t * 2] * RADF, lo = labels[t * 2 + 1] * RADF;
        float cl = cosf(la);
        g_label_xyz[t * 3 + 0] = cl * cosf(lo);
        g_label_xyz[t * 3 + 1] = cl * sinf(lo);
        g_label_xyz[t * 3 + 2] = sinf(la);
    }
    if (t < NTOT) {
        const float* src;
        if (t < NC)            src = cpart + (size_t)t * 2;
        else if (t < NC + NM)  src = mpart + (size_t)(t - NC) * 2;
        else                   src = fpart + (size_t)(t - NC - NM) * 2;
        float la = src[0] * RADF, lo = src[1] * RADF;
        float cl = cosf(la);
        g_part_xyz[t * 3 + 0] = cl * cosf(lo);
        g_part_xyz[t * 3 + 1] = cl * sinf(lo);
        g_part_xyz[t * 3 + 2] = sinf(la);
    }
    if (t < NF) g_gp[t] = mparents[fparents[t]];
    if (t < 5)  g_counts[t] = 0;
}

// ============================================================
// Kernel 2: label index per (head, b): argmin haversine == argmax 3D dot
// ============================================================
__global__ void k_labelidx()
{
    int t = blockIdx.x * blockDim.x + threadIdx.x;
    if (t >= 3 * B) return;
    int head = t >> 12;      // / 4096
    int b    = t & (B - 1);
    int base, n;
    if (head == 0)      { base = 0;       n = NC; }
    else if (head == 1) { base = NC;      n = NM; }
    else                { base = NC + NM; n = NF; }
    float lx = g_label_xyz[b * 3 + 0];
    float ly = g_label_xyz[b * 3 + 1];
    float lz = g_label_xyz[b * 3 + 2];
    const float* P = g_part_xyz + (size_t)base * 3;
    float best = -2.0f; int bi = 0;
    for (int i = 0; i < n; i++) {
        float d = lx * P[i * 3] + ly * P[i * 3 + 1] + lz * P[i * 3 + 2];
        if (d > best) { best = d; bi = i; }   // strict > keeps first index
    }
    g_label_idx[head * B + b] = bi;
}

// ============================================================
// Kernel 3: SGEMM 128x128x16, double-buffered smem, 8x8 per thread
// out[b,n] = sum_d A[b,d] * W[d,n] + bias[n]
// ============================================================
#define BM 128
#define BN 128
#define BK 16

__global__ __launch_bounds__(256, 2)
void k_gemm(const float* __restrict__ A, const float* __restrict__ W,
            const float* __restrict__ bias, int N, size_t outOff)
{
    __shared__ float As[2][BK][BM];   // transposed A tile
    __shared__ float Bs[2][BK][BN];

    float* out = g_logits + outOff;

    const int tid = threadIdx.x;
    const int tx  = tid & 15;
    const int ty  = tid >> 4;
    const int m0  = blockIdx.x * BM;
    const int n0  = blockIdx.y * BN;

    const int a_row = tid >> 2;          // 0..63
    const int a_k   = (tid & 3) * 4;     // 0,4,8,12
    const int b_k   = tid >> 5;          // 0..7
    const int b_n   = (tid & 31) * 4;    // 0..124

    const float* Aptr = A + (size_t)(m0 + a_row) * D + a_k;
    const bool nok = (n0 + b_n) < N;     // N % 4 == 0 for all heads
    const float4 z4 = make_float4(0.f, 0.f, 0.f, 0.f);

    float acc[8][8];
#pragma unroll
    for (int i = 0; i < 8; i++)
#pragma unroll
        for (int j = 0; j < 8; j++) acc[i][j] = 0.f;

    float4 a0, a1, bb0, bb1;

    // prologue: tile 0 -> buffer 0
    a0  = *(const float4*)(Aptr);
    a1  = *(const float4*)(Aptr + (size_t)64 * D);
    bb0 = nok ? *(const float4*)&W[(size_t)(b_k)     * N + n0 + b_n] : z4;
    bb1 = nok ? *(const float4*)&W[(size_t)(b_k + 8) * N + n0 + b_n] : z4;
    As[0][a_k + 0][a_row]      = a0.x;
    As[0][a_k + 1][a_row]      = a0.y;
    As[0][a_k + 2][a_row]      = a0.z;
    As[0][a_k + 3][a_row]      = a0.w;
    As[0][a_k + 0][a_row + 64] = a1.x;
    As[0][a_k + 1][a_row + 64] = a1.y;
    As[0][a_k + 2][a_row + 64] = a1.z;
    As[0][a_k + 3][a_row + 64] = a1.w;
    *(float4*)&Bs[0][b_k][b_n]     = bb0;
    *(float4*)&Bs[0][b_k + 8][b_n] = bb1;
    __syncthreads();

    const int NT = D / BK;   // 112
    int buf = 0;
    for (int t = 0; t < NT; t++) {
        if (t + 1 < NT) {
            int k0 = (t + 1) * BK;
            a0  = *(const float4*)(Aptr + k0);
            a1  = *(const float4*)(Aptr + (size_t)64 * D + k0);
            bb0 = nok ? *(const float4*)&W[(size_t)(k0 + b_k)     * N + n0 + b_n] : z4;
            bb1 = nok ? *(const float4*)&W[(size_t)(k0 + b_k + 8) * N + n0 + b_n] : z4;
        }
#pragma unroll
        for (int k = 0; k < BK; k++) {
            float av[8], bv[8];
            *(float4*)&av[0] = *(const float4*)&As[buf][k][ty * 8];
            *(float4*)&av[4] = *(const float4*)&As[buf][k][ty * 8 + 4];
            *(float4*)&bv[0] = *(const float4*)&Bs[buf][k][tx * 8];
            *(float4*)&bv[4] = *(const float4*)&Bs[buf][k][tx * 8 + 4];
#pragma unroll
            for (int i = 0; i < 8; i++)
#pragma unroll
                for (int j = 0; j < 8; j++)
                    acc[i][j] = fmaf(av[i], bv[j], acc[i][j]);
        }
        if (t + 1 < NT) {
            int nb = buf ^ 1;
            As[nb][a_k + 0][a_row]      = a0.x;
            As[nb][a_k + 1][a_row]      = a0.y;
            As[nb][a_k + 2][a_row]      = a0.z;
            As[nb][a_k + 3][a_row]      = a0.w;
            As[nb][a_k + 0][a_row + 64] = a1.x;
            As[nb][a_k + 1][a_row + 64] = a1.y;
            As[nb][a_k + 2][a_row + 64] = a1.z;
            As[nb][a_k + 3][a_row + 64] = a1.w;
            *(float4*)&Bs[nb][b_k][b_n]     = bb0;
            *(float4*)&Bs[nb][b_k + 8][b_n] = bb1;
        }
        __syncthreads();
        buf ^= 1;
    }

    // epilogue: + bias, guarded vectorized store
#pragma unroll
    for (int i = 0; i < 8; i++) {
        size_t ro = (size_t)(m0 + ty * 8 + i) * N;
#pragma unroll
        for (int jj = 0; jj < 8; jj += 4) {
            int n = n0 + tx * 8 + jj;
            if (n < N) {  // N%4==0 and n%4==0 => full float4 in-range
                float4 bsv = *(const float4*)&bias[n];
                float4 v;
                v.x = acc[i][jj + 0] + bsv.x;
                v.y = acc[i][jj + 1] + bsv.y;
                v.z = acc[i][jj + 2] + bsv.z;
                v.w = acc[i][jj + 3] + bsv.w;
                *(float4*)&out[ro + n] = v;
            }
        }
    }
}

// ============================================================
// Kernel 4: per (b, head): nll = logsumexp(row) - row[label]
// ============================================================
__global__ void k_nll()
{
    __shared__ float red[256];
    int b = blockIdx.x;
    int head = blockIdx.y;
    int n; size_t off;
    if (head == 0)      { n = NC; off = OFF_C; }
    else if (head == 1) { n = NM; off = OFF_M; }
    else                { n = NF; off = OFF_F; }
    const float* row = g_logits + off + (size_t)b * n;
    int tid = threadIdx.x;

    float m = -3.402823466e38f;
    for (int i = tid; i < n; i += 256) m = fmaxf(m, row[i]);
    red[tid] = m; __syncthreads();
    for (int s = 128; s > 0; s >>= 1) {
        if (tid < s) red[tid] = fmaxf(red[tid], red[tid + s]);
        __syncthreads();
    }
    m = red[0];
    __syncthreads();

    float sum = 0.f;
    for (int i = tid; i < n; i += 256) sum += __expf(row[i] - m);
    red[tid] = sum; __syncthreads();
    for (int s = 128; s > 0; s >>= 1) {
        if (tid < s) red[tid] += red[tid + s];
        __syncthreads();
    }
    if (tid == 0) {
        int li = g_label_idx[head * B + b];
        g_nll[head * B + b] = m + logf(red[0]) - row[li];
    }
}

// ============================================================
// Kernel 5: hierarchical argmax + haversine accuracy bins
// argmax_f fine[f] + mid[fp[f]] + coarse[gp[f]]  (lse terms constant per row)
// ============================================================
__global__ void k_predict(const float* __restrict__ labels,
                          const float* __restrict__ fpart,
                          const int*   __restrict__ fparents)
{
    __shared__ float sval[256];
    __shared__ int   sidx[256];
    int b = blockIdx.x, tid = threadIdx.x;
    const float* Fv = g_logits + OFF_F + (size_t)b * NF;
    const float* Mv = g_logits + OFF_M + (size_t)b * NM;
    const float* Cv = g_logits + OFF_C + (size_t)b * NC;

    float best = -3.402823466e38f; int bi = 0x7fffffff;
    for (int f = tid; f < NF; f += 256) {
        float s = Fv[f] + Mv[fparents[f]] + Cv[g_gp[f]];
        if (s > best) { best = s; bi = f; }
    }
    sval[tid] = best; sidx[tid] = bi;
    __syncthreads();
    for (int s = 128; s > 0; s >>= 1) {
        if (tid < s) {
            if (sval[tid + s] > sval[tid] ||
                (sval[tid + s] == sval[tid] && sidx[tid + s] < sidx[tid])) {
                sval[tid] = sval[tid + s];
                sidx[tid] = sidx[tid + s];
            }
        }
        __syncthreads();
    }
    if (tid == 0) {
        int p = sidx[0];
        const float RADF = 0.017453292519943295f;
        float lat1 = labels[b * 2]     * RADF;
        float lon1 = labels[b * 2 + 1] * RADF;
        float lat2 = fpart[p * 2]      * RADF;
        float lon2 = fpart[p * 2 + 1]  * RADF;
        float sdlat = sinf((lat2 - lat1) * 0.5f);
        float sdlon = sinf((lon2 - lon1) * 0.5f);
        float a = sdlat * sdlat + cosf(lat1) * cosf(lat2) * sdlon * sdlon;
        a = fminf(fmaxf(a, 0.f), 1.f);
        float d = 2.0f * 6371.0f * asinf(sqrtf(a));
        if (d <= 1.0f)    atomicAdd(&g_counts[0], 1);
        if (d <= 25.0f)   atomicAdd(&g_counts[1], 1);
        if (d <= 200.0f)  atomicAdd(&g_counts[2], 1);
        if (d <= 750.0f)  atomicAdd(&g_counts[3], 1);
        if (d <= 2500.0f) atomicAdd(&g_counts[4], 1);
    }
}

// ============================================================
// Kernel 6: deterministic final reduction -> out[0]=loss, out[1..5]=acc
// ============================================================
__global__ void k_finalize(float* __restrict__ out)
{
    __shared__ float red[256];
    int tid = threadIdx.x;
    float s = 0.f;
    for (int i = tid; i < 3 * B; i += 256) s += g_nll[i];
    red[tid] = s; __syncthreads();
    for (int st = 128; st > 0; st >>= 1) {
        if (tid < st) red[tid] += red[tid + st];
        __syncthreads();
    }
    if (tid == 0) out[0] = red[0] / (float)B;
    if (tid < 5)  out[1 + tid] = (float)g_counts[tid] / (float)B;
}

// ============================================================
extern "C" void kernel_launch(void* const* d_in, const int* in_sizes, int n_in,
                              void* d_out, int out_size)
{
    const float* features = (const float*)d_in[0];
    const float* labels   = (const float*)d_in[1];
    const float* cpart    = (const float*)d_in[2];
    const float* mpart    = (const float*)d_in[3];
    const float* fpart    = (const float*)d_in[4];
    const int*   mparents = (const int*)d_in[5];
    const int*   fparents = (const int*)d_in[6];
    const float* cw = (const float*)d_in[7];
    const float* cb = (const float*)d_in[8];
    const float* mw = (const float*)d_in[9];
    const float* mb = (const float*)d_in[10];
    const float* fw = (const float*)d_in[11];
    const float* fb = (const float*)d_in[12];
    float* out = (float*)d_out;

    k_init<<<(NTOT + 255) / 256, 256>>>(labels, cpart, mpart, fpart, mparents, fparents);
    k_labelidx<<<(3 * B + 255) / 256, 256>>>();

    dim3 gC(B / BM, (NC + BN - 1) / BN);
    dim3 gM(B / BM, (NM + BN - 1) / BN);
    dim3 gF(B / BM, (NF + BN - 1) / BN);
    k_gemm<<<gC, 256>>>(features, cw, cb, NC, OFF_C);
    k_gemm<<<gM, 256>>>(features, mw, mb, NM, OFF_M);
    k_gemm<<<gF, 256>>>(features, fw, fb, NF, OFF_F);

    k_nll<<<dim3(B, 3), 256>>>();
    k_predict<<<B, 256>>>(labels, fpart, fparents);
    k_finalize<<<1, 256>>>(out);
}

// round 3
// speedup vs baseline: 2.3138x; 2.3138x over previous
#include <cuda_runtime.h>
#include <cuda_bf16.h>
#include <math.h>
#include <stdint.h>

#define B  4096
#define D  1792
#define NC 3000
#define NM 7000
#define NF 13000
#define NTOT (NC + NM + NF)

// padded (tile-128) class counts for the transposed weight buffers
#define NPC 3072
#define NPM 7040
#define NPF 13056
#define SEC_C 0
#define SEC_M 3072
#define SEC_F 10112
#define NPTOT 23168

#define OFF_C ((size_t)0)
#define OFF_M ((size_t)B * NC)
#define OFF_F (OFF_M + (size_t)B * NM)

// ---- device scratch (no runtime allocation allowed) ----
__device__ float         g_logits[(size_t)B * NTOT];   // ~377 MB
__device__ __nv_bfloat16 g_A_hi[(size_t)B * D];
__device__ __nv_bfloat16 g_A_lo[(size_t)B * D];
__device__ __nv_bfloat16 g_Wt_hi[(size_t)NPTOT * D];   // transposed [n][k]
__device__ __nv_bfloat16 g_Wt_lo[(size_t)NPTOT * D];
__device__ float g_label_xyz[B * 3];
__device__ float g_part_xyz[NTOT * 3];
__device__ int   g_gp[NF];
__device__ int   g_label_idx[3 * B];
__device__ float g_nll[B];
__device__ int   g_counts[5];

// ============================================================
// helpers
// ============================================================
__device__ __forceinline__ uint32_t smem_to_u32(const void* p) {
    uint32_t a;
    asm("{ .reg .u64 t; cvta.to.shared.u64 t, %1; cvt.u32.u64 %0, t; }"
        : "=r"(a) : "l"(p));
    return a;
}
#define CP_ASYNC16(sm, gp) \
    asm volatile("cp.async.cg.shared.global [%0], [%1], 16;" :: "r"(sm), "l"(gp) : "memory")

__device__ __forceinline__ void ldsm_x4(uint32_t* r, uint32_t addr) {
    asm volatile("ldmatrix.sync.aligned.m8n8.x4.shared.b16 {%0,%1,%2,%3}, [%4];"
        : "=r"(r[0]), "=r"(r[1]), "=r"(r[2]), "=r"(r[3]) : "r"(addr));
}
__device__ __forceinline__ void mma_bf16(float* d, const uint32_t* a, const uint32_t* b) {
    asm volatile("mma.sync.aligned.m16n8k16.row.col.f32.bf16.bf16.f32 "
        "{%0,%1,%2,%3}, {%4,%5,%6,%7}, {%8,%9}, {%0,%1,%2,%3};"
        : "+f"(d[0]), "+f"(d[1]), "+f"(d[2]), "+f"(d[3])
        : "r"(a[0]), "r"(a[1]), "r"(a[2]), "r"(a[3]), "r"(b[0]), "r"(b[1]));
}

// ============================================================
// Kernel: precompute unit vectors, grandparents, zero counters
// ============================================================
__global__ void k_init(const float* __restrict__ labels,
                       const float* __restrict__ cpart,
                       const float* __restrict__ mpart,
                       const float* __restrict__ fpart,
                       const int*   __restrict__ mparents,
                       const int*   __restrict__ fparents)
{
    int t = blockIdx.x * blockDim.x + threadIdx.x;
    const float RADF = 0.017453292519943295f;
    if (t < B) {
        float la = labels[t * 2] * RADF, lo = labels[t * 2 + 1] * RADF;
        float cl = cosf(la);
        g_label_xyz[t * 3 + 0] = cl * cosf(lo);
        g_label_xyz[t * 3 + 1] = cl * sinf(lo);
        g_label_xyz[t * 3 + 2] = sinf(la);
    }
    if (t < NTOT) {
        const float* src;
        if (t < NC)            src = cpart + (size_t)t * 2;
        else if (t < NC + NM)  src = mpart + (size_t)(t - NC) * 2;
        else                   src = fpart + (size_t)(t - NC - NM) * 2;
        float la = src[0] * RADF, lo = src[1] * RADF;
        float cl = cosf(la);
        g_part_xyz[t * 3 + 0] = cl * cosf(lo);
        g_part_xyz[t * 3 + 1] = cl * sinf(lo);
        g_part_xyz[t * 3 + 2] = sinf(la);
    }
    if (t < NF) g_gp[t] = mparents[fparents[t]];
    if (t < 5)  g_counts[t] = 0;
}

// ============================================================
// Kernel: label index per (head, b): argmin haversine == argmax 3D dot
// ============================================================
__global__ void k_labelidx()
{
    int t = blockIdx.x * blockDim.x + threadIdx.x;
    if (t >= 3 * B) return;
    int head = t >> 12;
    int b    = t & (B - 1);
    int base, n;
    if (head == 0)      { base = 0;       n = NC; }
    else if (head == 1) { base = NC;      n = NM; }
    else                { base = NC + NM; n = NF; }
    float lx = g_label_xyz[b * 3 + 0];
    float ly = g_label_xyz[b * 3 + 1];
    float lz = g_label_xyz[b * 3 + 2];
    const float* P = g_part_xyz + (size_t)base * 3;
    float best = -2.0f; int bi = 0;
    for (int i = 0; i < n; i++) {
        float d = lx * P[i * 3] + ly * P[i * 3 + 1] + lz * P[i * 3 + 2];
        if (d > best) { best = d; bi = i; }
    }
    g_label_idx[head * B + b] = bi;
}

// ============================================================
// Kernel: convert features -> bf16 hi/lo
// ============================================================
__global__ void k_convA(const float* __restrict__ A)
{
    int t = blockIdx.x * blockDim.x + threadIdx.x;
    if (t >= B * D) return;
    float v = A[t];
    __nv_bfloat16 h = __float2bfloat16(v);
    __nv_bfloat16 l = __float2bfloat16(v - __bfloat162float(h));
    g_A_hi[t] = h;
    g_A_lo[t] = l;
}

// ============================================================
// Kernel: transpose + convert W [D][N] -> Wt [NPAD][D] bf16 hi/lo (zero pad)
// ============================================================
__global__ void k_convW(const float* __restrict__ W, int N, int secOff)
{
    __shared__ float t[32][33];
    int k0 = blockIdx.x * 32, n0 = blockIdx.y * 32;
#pragma unroll
    for (int j = 0; j < 32; j += 8) {
        int k = k0 + threadIdx.y + j;
        int n = n0 + threadIdx.x;
        t[threadIdx.y + j][threadIdx.x] = (n < N) ? W[(size_t)k * N + n] : 0.f;
    }
    __syncthreads();
#pragma unroll
    for (int j = 0; j < 32; j += 8) {
        int n = n0 + threadIdx.y + j;
        int k = k0 + threadIdx.x;
        float v = t[threadIdx.x][threadIdx.y + j];
        __nv_bfloat16 h = __float2bfloat16(v);
        __nv_bfloat16 l = __float2bfloat16(v - __bfloat162float(h));
        size_t o = (size_t)(secOff + n) * D + k;
        g_Wt_hi[o] = h;
        g_Wt_lo[o] = l;
    }
}

// ============================================================
// bf16x3 GEMM via mma.sync: 256x128 tile, BK=64, 3-stage cp.async pipe
// acc(fp32, regs) += Ah*Bh (pass0) + Ah*Bl (pass1) + Al*Bh (pass2)
// ============================================================
#define BM 256
#define BN 128
#define BK 64
#define NS 3
#define STAGE_A 32768          // 256 rows * 128B
#define STAGE_BYTES 49152      // A 32KB + B 16KB
#define NKC (D / BK)           // 28
#define NCHUNK (3 * NKC)       // 84

__global__ __launch_bounds__(512, 1)
void k_mmagemm(const float* __restrict__ bias, int N, int secOff, size_t outOff)
{
    extern __shared__ __align__(1024) char smem[];
    uint32_t sb = smem_to_u32(smem);
    const int tid  = threadIdx.x;
    const int wid  = tid >> 5;
    const int lane = tid & 31;
    const int wm   = wid >> 2;     // 0..3
    const int wn   = wid & 3;      // 0..3
    const int m0   = blockIdx.x * BM;
    const int n0   = blockIdx.y * BN;

    // ---- cp.async per-thread addressing (swizzled SW128, 128B rows) ----
    uint32_t aSw[4]; size_t aGo[4];
#pragma unroll
    for (int i = 0; i < 4; i++) {
        int idx = tid + i * 512;          // 0..2047
        int row = idx >> 3, seg = idx & 7;
        aSw[i] = (uint32_t)(row * 128 + ((seg * 16) ^ ((row & 7) << 4)));
        aGo[i] = (size_t)row * D + seg * 8;
    }
    uint32_t bSw[2]; size_t bGo[2];
#pragma unroll
    for (int i = 0; i < 2; i++) {
        int idx = tid + i * 512;          // 0..1023
        int row = idx >> 3, seg = idx & 7;
        bSw[i] = (uint32_t)(row * 128 + ((seg * 16) ^ ((row & 7) << 4)));
        bGo[i] = (size_t)row * D + seg * 8;
    }
    const __nv_bfloat16* Ah = g_A_hi + (size_t)m0 * D;
    const __nv_bfloat16* Al = g_A_lo + (size_t)m0 * D;
    const __nv_bfloat16* Bh = g_Wt_hi + (size_t)(secOff + n0) * D;
    const __nv_bfloat16* Bl = g_Wt_lo + (size_t)(secOff + n0) * D;

    // ---- ldmatrix per-lane addressing ----
    // A: per m-tile, x4 covers m16 x k16 (matrices: rows m..m+7 k0 | m+8..15 k0 | m..m+7 k0+8 | m+8..15 k0+8)
    uint32_t aTerm[4], aXor[4];
#pragma unroll
    for (int mt = 0; mt < 4; mt++) {
        int row = wm * 64 + mt * 16 + (lane & 7) + ((lane >> 3) & 1) * 8;
        aTerm[mt] = (uint32_t)(row * 128);
        aXor[mt]  = (uint32_t)((row & 7) << 4);
    }
    const uint32_t aCSel = ((lane >> 4) & 1) * 16;
    // B: per n-pair, x4 covers n16 x k16 (matrices: n..n+7 k0 | n..n+7 k0+8 | n+8..15 k0 | n+8..15 k0+8)
    uint32_t bTerm[2], bXor[2];
#pragma unroll
    for (int np = 0; np < 2; np++) {
        int row = wn * 32 + np * 16 + (lane & 7) + ((lane >> 4) & 1) * 8;
        bTerm[np] = (uint32_t)(row * 128);
        bXor[np]  = (uint32_t)((row & 7) << 4);
    }
    const uint32_t bCSel = ((lane >> 3) & 1) * 16;

    float acc[4][4][4];
#pragma unroll
    for (int i = 0; i < 4; i++)
#pragma unroll
        for (int j = 0; j < 4; j++)
#pragma unroll
            for (int k = 0; k < 4; k++) acc[i][j][k] = 0.f;

    // ---- pipeline ----
#define ISSUE(c) do { \
        int _c = (c); \
        int pass = _c / NKC, kc = (_c % NKC) * BK; \
        const __nv_bfloat16* aS = (pass < 2 ? Ah : Al) + kc; \
        const __nv_bfloat16* bS = (pass == 1 ? Bl : Bh) + kc; \
        uint32_t st = sb + (uint32_t)(_c % NS) * STAGE_BYTES; \
        CP_ASYNC16(st + aSw[0], aS + aGo[0]); \
        CP_ASYNC16(st + aSw[1], aS + aGo[1]); \
        CP_ASYNC16(st + aSw[2], aS + aGo[2]); \
        CP_ASYNC16(st + aSw[3], aS + aGo[3]); \
        CP_ASYNC16(st + STAGE_A + bSw[0], bS + bGo[0]); \
        CP_ASYNC16(st + STAGE_A + bSw[1], bS + bGo[1]); \
    } while (0)

    ISSUE(0); asm volatile("cp.async.commit_group;" ::: "memory");
    ISSUE(1); asm volatile("cp.async.commit_group;" ::: "memory");

    for (int c = 0; c < NCHUNK; c++) {
        if (c + 2 < NCHUNK) ISSUE(c + 2);
        asm volatile("cp.async.commit_group;" ::: "memory");
        asm volatile("cp.async.wait_group 2;" ::: "memory");
        __syncthreads();
        uint32_t stA = sb + (uint32_t)(c % NS) * STAGE_BYTES;
        uint32_t stB = stA + STAGE_A;
#pragma unroll
        for (int ks = 0; ks < 4; ks++) {
            uint32_t a[4][4], b[2][4];
            const uint32_t kb = (uint32_t)(ks * 32);
#pragma unroll
            for (int mt = 0; mt < 4; mt++)
                ldsm_x4(a[mt], stA + aTerm[mt] + ((kb + aCSel) ^ aXor[mt]));
#pragma unroll
            for (int np = 0; np < 2; np++)
                ldsm_x4(b[np], stB + bTerm[np] + ((kb + bCSel) ^ bXor[np]));
#pragma unroll
            for (int mt = 0; mt < 4; mt++) {
#pragma unroll
                for (int nt = 0; nt < 4; nt++)
                    mma_bf16(acc[mt][nt], a[mt], &b[nt >> 1][(nt & 1) * 2]);
            }
        }
        __syncthreads();
    }
#undef ISSUE

    // ---- epilogue: add bias, store fp32 logits ----
    float* out = g_logits + outOff;
    const int rbase = m0 + wm * 64 + (lane >> 2);
    const int cbase = n0 + wn * 32 + (lane & 3) * 2;
#pragma unroll
    for (int mt = 0; mt < 4; mt++) {
#pragma unroll
        for (int nt = 0; nt < 4; nt++) {
            int col = cbase + nt * 8;
            if (col < N) {
                float bx = bias[col], by = bias[col + 1];
                int r0 = rbase + mt * 16;
                float2 v0 = { acc[mt][nt][0] + bx, acc[mt][nt][1] + by };
                float2 v1 = { acc[mt][nt][2] + bx, acc[mt][nt][3] + by };
                *(float2*)&out[(size_t)r0 * N + col]       = v0;
                *(float2*)&out[(size_t)(r0 + 8) * N + col] = v1;
            }
        }
    }
}

// ============================================================
// Fused tail: per row b — 3 logsumexps + NLL + hierarchical argmax + acc bins
// ============================================================
__device__ float block_lse(const float* v, int n, float* red)
{
    int tid = threadIdx.x;
    float m = -3.402823466e38f;
    for (int i = tid; i < n; i += 256) m = fmaxf(m, v[i]);
    red[tid] = m; __syncthreads();
    for (int s = 128; s > 0; s >>= 1) {
        if (tid < s) red[tid] = fmaxf(red[tid], red[tid + s]);
        __syncthreads();
    }
    m = red[0]; __syncthreads();
    float sum = 0.f;
    for (int i = tid; i < n; i += 256) sum += __expf(v[i] - m);
    red[tid] = sum; __syncthreads();
    for (int s = 128; s > 0; s >>= 1) {
        if (tid < s) red[tid] += red[tid + s];
        __syncthreads();
    }
    float r = m + logf(red[0]);
    __syncthreads();
    return r;
}

__global__ __launch_bounds__(256)
void k_tail(const float* __restrict__ labels,
            const float* __restrict__ fpart,
            const int*   __restrict__ fparents)
{
    __shared__ float sC[NC];
    __shared__ float sM[NM];
    __shared__ float rA[256];
    __shared__ float rB[256];
    __shared__ int   rI[256];

    int b = blockIdx.x, tid = threadIdx.x;
    const float* Cv = g_logits + OFF_C + (size_t)b * NC;
    const float* Mv = g_logits + OFF_M + (size_t)b * NM;
    const float* Fv = g_logits + OFF_F + (size_t)b * NF;

    for (int i = tid; i < NC; i += 256) sC[i] = Cv[i];
    for (int i = tid; i < NM; i += 256) sM[i] = Mv[i];
    __syncthreads();

    float lseC = block_lse(sC, NC, rA);
    float lseM = block_lse(sM, NM, rA);

    // single pass over fine logits: online LSE + hierarchical argmax
    float mF = -3.402823466e38f, sF = 0.f;
    float best = -3.402823466e38f; int bi = 0x7fffffff;
    for (int f = tid; f < NF; f += 256) {
        float v = Fv[f];
        float score = v + sM[fparents[f]] + sC[g_gp[f]];
        if (score > best) { best = score; bi = f; }
        if (v > mF) { sF = sF * __expf(mF - v) + 1.f; mF = v; }
        else        { sF += __expf(v - mF); }
    }
    rA[tid] = best; rI[tid] = bi;
    __syncthreads();
    for (int s = 128; s > 0; s >>= 1) {
        if (tid < s) {
            if (rA[tid + s] > rA[tid] ||
                (rA[tid + s] == rA[tid] && rI[tid + s] < rI[tid])) {
                rA[tid] = rA[tid + s]; rI[tid] = rI[tid + s];
            }
        }
        __syncthreads();
    }
    int pred = rI[0];
    __syncthreads();

    rA[tid] = mF; rB[tid] = sF;
    __syncthreads();
    for (int s = 128; s > 0; s >>= 1) {
        if (tid < s) {
            float m2 = rA[tid + s], s2 = rB[tid + s];
            float M = fmaxf(rA[tid], m2);
            rB[tid] = rB[tid] * __expf(rA[tid] - M) + s2 * __expf(m2 - M);
            rA[tid] = M;
        }
        __syncthreads();
    }

    if (tid == 0) {
        float lseF = rA[0] + logf(rB[0]);
        int liC = g_label_idx[b];
        int liM = g_label_idx[B + b];
        int liF = g_label_idx[2 * B + b];
        g_nll[b] = (lseC - sC[liC]) + (lseM - sM[liM]) + (lseF - Fv[liF]);

        const float RADF = 0.017453292519943295f;
        float lat1 = labels[b * 2]       * RADF;
        float lon1 = labels[b * 2 + 1]   * RADF;
        float lat2 = fpart[pred * 2]     * RADF;
        float lon2 = fpart[pred * 2 + 1] * RADF;
        float sdlat = sinf((lat2 - lat1) * 0.5f);
        float sdlon = sinf((lon2 - lon1) * 0.5f);
        float a = sdlat * sdlat + cosf(lat1) * cosf(lat2) * sdlon * sdlon;
        a = fminf(fmaxf(a, 0.f), 1.f);
        float d = 2.0f * 6371.0f * asinf(sqrtf(a));
        if (d <= 1.0f)    atomicAdd(&g_counts[0], 1);
        if (d <= 25.0f)   atomicAdd(&g_counts[1], 1);
        if (d <= 200.0f)  atomicAdd(&g_counts[2], 1);
        if (d <= 750.0f)  atomicAdd(&g_counts[3], 1);
        if (d <= 2500.0f) atomicAdd(&g_counts[4], 1);
    }
}

// ============================================================
// Final deterministic reduction -> out[0]=loss, out[1..5]=acc
// ============================================================
__global__ void k_finalize(float* __restrict__ out)
{
    __shared__ float red[256];
    int tid = threadIdx.x;
    float s = 0.f;
    for (int i = tid; i < B; i += 256) s += g_nll[i];
    red[tid] = s; __syncthreads();
    for (int st = 128; st > 0; st >>= 1) {
        if (tid < st) red[tid] += red[tid + st];
        __syncthreads();
    }
    if (tid == 0) out[0] = red[0] / (float)B;
    if (tid < 5)  out[1 + tid] = (float)g_counts[tid] / (float)B;
}

// ============================================================
extern "C" void kernel_launch(void* const* d_in, const int* in_sizes, int n_in,
                              void* d_out, int out_size)
{
    const float* features = (const float*)d_in[0];
    const float* labels   = (const float*)d_in[1];
    const float* cpart    = (const float*)d_in[2];
    const float* mpart    = (const float*)d_in[3];
    const float* fpart    = (const float*)d_in[4];
    const int*   mparents = (const int*)d_in[5];
    const int*   fparents = (const int*)d_in[6];
    const float* cw = (const float*)d_in[7];
    const float* cb = (const float*)d_in[8];
    const float* mw = (const float*)d_in[9];
    const float* mb = (const float*)d_in[10];
    const float* fw = (const float*)d_in[11];
    const float* fb = (const float*)d_in[12];
    float* out = (float*)d_out;

    static int s_attr_done = 0;
    if (!s_attr_done) {
        cudaFuncSetAttribute(k_mmagemm, cudaFuncAttributeMaxDynamicSharedMemorySize,
                             NS * STAGE_BYTES);
        s_attr_done = 1;
    }

    k_init<<<(NTOT + 255) / 256, 256>>>(labels, cpart, mpart, fpart, mparents, fparents);
    k_labelidx<<<(3 * B + 255) / 256, 256>>>();

    k_convA<<<(B * D + 255) / 256, 256>>>(features);
    dim3 tb(32, 8);
    k_convW<<<dim3(D / 32, NPC / 32), tb>>>(cw, NC, SEC_C);
    k_convW<<<dim3(D / 32, NPM / 32), tb>>>(mw, NM, SEC_M);
    k_convW<<<dim3(D / 32, NPF / 32), tb>>>(fw, NF, SEC_F);

    k_mmagemm<<<dim3(B / BM, NPC / BN), 512, NS * STAGE_BYTES>>>(cb, NC, SEC_C, OFF_C);
    k_mmagemm<<<dim3(B / BM, NPM / BN), 512, NS * STAGE_BYTES>>>(mb, NM, SEC_M, OFF_M);
    k_mmagemm<<<dim3(B / BM, NPF / BN), 512, NS * STAGE_BYTES>>>(fb, NF, SEC_F, OFF_F);

    k_tail<<<B, 256>>>(labels, fpart, fparents);
    k_finalize<<<1, 256>>>(out);
}

// round 4
// speedup vs baseline: 2.7049x; 1.1690x over previous
#include <cuda_runtime.h>
#include <cuda_bf16.h>
#include <math.h>
#include <stdint.h>

#define B  4096
#define D  1792
#define NC 3000
#define NM 7000
#define NF 13000
#define NTOT (NC + NM + NF)

// padded (tile-128) class counts for the transposed weight buffers
#define NPC 3072
#define NPM 7040
#define NPF 13056
#define SEC_C 0
#define SEC_M 3072
#define SEC_F 10112
#define NPTOT 23168

#define OFF_C ((size_t)0)
#define OFF_M ((size_t)B * NC)
#define OFF_F (OFF_M + (size_t)B * NM)

// ---- device scratch (no runtime allocation allowed) ----
__device__ float         g_logits[(size_t)B * NTOT];   // ~377 MB
__device__ __nv_bfloat16 g_A_hi[(size_t)B * D];
__device__ __nv_bfloat16 g_A_lo[(size_t)B * D];
__device__ __nv_bfloat16 g_Wt_hi[(size_t)NPTOT * D];   // transposed [n][k]
__device__ __nv_bfloat16 g_Wt_lo[(size_t)NPTOT * D];
__device__ float g_label_xyz[B * 3];
__device__ float g_part_xyz[NTOT * 3];
__device__ int   g_gp[NF];
__device__ int   g_label_idx[3 * B];
__device__ float g_nll[B];
__device__ int   g_counts[5];

// ============================================================
// helpers
// ============================================================
__device__ __forceinline__ uint32_t smem_to_u32(const void* p) {
    uint32_t a;
    asm("{ .reg .u64 t; cvta.to.shared.u64 t, %1; cvt.u32.u64 %0, t; }"
        : "=r"(a) : "l"(p));
    return a;
}
#define CP_ASYNC16(sm, gp) \
    asm volatile("cp.async.cg.shared.global [%0], [%1], 16;" :: "r"(sm), "l"(gp) : "memory")

__device__ __forceinline__ void ldsm_x4(uint32_t* r, uint32_t addr) {
    asm volatile("ldmatrix.sync.aligned.m8n8.x4.shared.b16 {%0,%1,%2,%3}, [%4];"
        : "=r"(r[0]), "=r"(r[1]), "=r"(r[2]), "=r"(r[3]) : "r"(addr));
}
__device__ __forceinline__ void mma_bf16(float* d, const uint32_t* a, const uint32_t* b) {
    asm volatile("mma.sync.aligned.m16n8k16.row.col.f32.bf16.bf16.f32 "
        "{%0,%1,%2,%3}, {%4,%5,%6,%7}, {%8,%9}, {%0,%1,%2,%3};"
        : "+f"(d[0]), "+f"(d[1]), "+f"(d[2]), "+f"(d[3])
        : "r"(a[0]), "r"(a[1]), "r"(a[2]), "r"(a[3]), "r"(b[0]), "r"(b[1]));
}

// fast e^x on the fma/alu pipes (x <= 0; flushes to ~0 below -80)
__device__ __forceinline__ float exp_fast(float x) {
    x = fmaxf(x, -80.0f);
    float t = x * 1.4426950408889634f;
    int   e = __float2int_rn(t);
    float f = t - (float)e;
    float y = f * 0.6931471805599453f;
    float p = 8.3333333e-3f;
    p = fmaf(p, y, 4.1666667e-2f);
    p = fmaf(p, y, 1.6666667e-1f);
    p = fmaf(p, y, 0.5f);
    p = fmaf(p, y, 1.0f);
    p = fmaf(p, y, 1.0f);
    return __int_as_float((e + 127) << 23) * p;
}

// ============================================================
// Kernel: precompute unit vectors, grandparents, zero counters
// ============================================================
__global__ void k_init(const float* __restrict__ labels,
                       const float* __restrict__ cpart,
                       const float* __restrict__ mpart,
                       const float* __restrict__ fpart,
                       const int*   __restrict__ mparents,
                       const int*   __restrict__ fparents)
{
    int t = blockIdx.x * blockDim.x + threadIdx.x;
    const float RADF = 0.017453292519943295f;
    if (t < B) {
        float la = labels[t * 2] * RADF, lo = labels[t * 2 + 1] * RADF;
        float cl = cosf(la);
        g_label_xyz[t * 3 + 0] = cl * cosf(lo);
        g_label_xyz[t * 3 + 1] = cl * sinf(lo);
        g_label_xyz[t * 3 + 2] = sinf(la);
    }
    if (t < NTOT) {
        const float* src;
        if (t < NC)            src = cpart + (size_t)t * 2;
        else if (t < NC + NM)  src = mpart + (size_t)(t - NC) * 2;
        else                   src = fpart + (size_t)(t - NC - NM) * 2;
        float la = src[0] * RADF, lo = src[1] * RADF;
        float cl = cosf(la);
        g_part_xyz[t * 3 + 0] = cl * cosf(lo);
        g_part_xyz[t * 3 + 1] = cl * sinf(lo);
        g_part_xyz[t * 3 + 2] = sinf(la);
    }
    if (t < NF) g_gp[t] = mparents[fparents[t]];
    if (t < 5)  g_counts[t] = 0;
}

// ============================================================
// Kernel: label index — one WARP per (head, b), shfl argmax reduce
// ============================================================
__global__ __launch_bounds__(256)
void k_labelidx()
{
    int gw = blockIdx.x * 8 + (threadIdx.x >> 5);   // global warp id, 0..3*B-1
    if (gw >= 3 * B) return;
    int lane = threadIdx.x & 31;
    int head = gw >> 12;
    int b    = gw & (B - 1);
    int base, n;
    if (head == 0)      { base = 0;       n = NC; }
    else if (head == 1) { base = NC;      n = NM; }
    else                { base = NC + NM; n = NF; }
    float lx = g_label_xyz[b * 3 + 0];
    float ly = g_label_xyz[b * 3 + 1];
    float lz = g_label_xyz[b * 3 + 2];
    const float* P = g_part_xyz + (size_t)base * 3;
    float best = -2.0f; int bi = 0x7fffffff;
    for (int i = lane; i < n; i += 32) {
        float d = lx * P[i * 3] + ly * P[i * 3 + 1] + lz * P[i * 3 + 2];
        if (d > best || (d == best && i < bi)) { best = d; bi = i; }
    }
#pragma unroll
    for (int off = 16; off > 0; off >>= 1) {
        float ob = __shfl_down_sync(0xffffffffu, best, off);
        int   oi = __shfl_down_sync(0xffffffffu, bi,   off);
        if (ob > best || (ob == best && oi < bi)) { best = ob; bi = oi; }
    }
    if (lane == 0) g_label_idx[head * B + b] = bi;
}

// ============================================================
// Kernel: convert features -> bf16 hi/lo (launched twice, half each)
// ============================================================
__global__ void k_convA(const float* __restrict__ A, int off)
{
    int t = off + blockIdx.x * blockDim.x + threadIdx.x;
    if (t >= B * D) return;
    float v = A[t];
    __nv_bfloat16 h = __float2bfloat16(v);
    __nv_bfloat16 l = __float2bfloat16(v - __bfloat162float(h));
    g_A_hi[t] = h;
    g_A_lo[t] = l;
}

// ============================================================
// Kernel: fused transpose+convert for ALL heads:
// W [D][N] -> Wt [NPTOT][D] bf16 hi/lo (zero pad)
// ============================================================
__global__ void k_convW(const float* __restrict__ cw,
                        const float* __restrict__ mw,
                        const float* __restrict__ fw)
{
    __shared__ float t[32][33];
    int k0 = blockIdx.x * 32;
    int ng0 = blockIdx.y * 32;              // global padded n
    const float* W; int N, sec;
    if (ng0 < SEC_M)      { W = cw; N = NC; sec = SEC_C; }
    else if (ng0 < SEC_F) { W = mw; N = NM; sec = SEC_M; }
    else                  { W = fw; N = NF; sec = SEC_F; }
    int n0 = ng0 - sec;
#pragma unroll
    for (int j = 0; j < 32; j += 8) {
        int k = k0 + threadIdx.y + j;
        int n = n0 + threadIdx.x;
        t[threadIdx.y + j][threadIdx.x] = (n < N) ? W[(size_t)k * N + n] : 0.f;
    }
    __syncthreads();
#pragma unroll
    for (int j = 0; j < 32; j += 8) {
        int n = ng0 + threadIdx.y + j;      // global padded row
        int k = k0 + threadIdx.x;
        float v = t[threadIdx.x][threadIdx.y + j];
        __nv_bfloat16 h = __float2bfloat16(v);
        __nv_bfloat16 l = __float2bfloat16(v - __bfloat162float(h));
        size_t o = (size_t)n * D + k;
        g_Wt_hi[o] = h;
        g_Wt_lo[o] = l;
    }
}

// ============================================================
// Fused bf16x3 GEMM via mma.sync: one launch for all 3 heads.
// 256x128 tile, BK=64, 3-stage cp.async pipe, ONE sync per chunk.
// ============================================================
#define BM 256
#define BN 128
#define BK 64
#define NS 3
#define STAGE_A 32768          // 256 rows * 128B
#define STAGE_BYTES 49152      // A 32KB + B 16KB
#define NKC (D / BK)           // 28
#define NCHUNK (3 * NKC)       // 84

__global__ __launch_bounds__(512, 1)
void k_mmagemm(const float* __restrict__ cb, const float* __restrict__ mb,
               const float* __restrict__ fb)
{
    extern __shared__ __align__(1024) char smem[];
    uint32_t sb = smem_to_u32(smem);
    const int tid  = threadIdx.x;
    const int wid  = tid >> 5;
    const int lane = tid & 31;
    const int wm   = wid >> 2;
    const int wn   = wid & 3;
    const int m0   = blockIdx.x * BM;
    const int n0   = blockIdx.y * BN;       // global padded col

    // head resolution
    int N, sec; size_t outOff; const float* bias;
    if (n0 < SEC_M)      { N = NC; sec = SEC_C; outOff = OFF_C; bias = cb; }
    else if (n0 < SEC_F) { N = NM; sec = SEC_M; outOff = OFF_M; bias = mb; }
    else                 { N = NF; sec = SEC_F; outOff = OFF_F; bias = fb; }
    const int nloc0 = n0 - sec;

    // ---- cp.async per-thread addressing (swizzled SW128, 128B rows) ----
    uint32_t aSw[4]; size_t aGo[4];
#pragma unroll
    for (int i = 0; i < 4; i++) {
        int idx = tid + i * 512;
        int row = idx >> 3, seg = idx & 7;
        aSw[i] = (uint32_t)(row * 128 + ((seg * 16) ^ ((row & 7) << 4)));
        aGo[i] = (size_t)row * D + seg * 8;
    }
    uint32_t bSw[2]; size_t bGo[2];
#pragma unroll
    for (int i = 0; i < 2; i++) {
        int idx = tid + i * 512;
        int row = idx >> 3, seg = idx & 7;
        bSw[i] = (uint32_t)(row * 128 + ((seg * 16) ^ ((row & 7) << 4)));
        bGo[i] = (size_t)row * D + seg * 8;
    }
    const __nv_bfloat16* Ah = g_A_hi + (size_t)m0 * D;
    const __nv_bfloat16* Al = g_A_lo + (size_t)m0 * D;
    const __nv_bfloat16* Bh = g_Wt_hi + (size_t)n0 * D;
    const __nv_bfloat16* Bl = g_Wt_lo + (size_t)n0 * D;

    // ---- ldmatrix per-lane addressing ----
    uint32_t aTerm[4], aXor[4];
#pragma unroll
    for (int mt = 0; mt < 4; mt++) {
        int row = wm * 64 + mt * 16 + (lane & 7) + ((lane >> 3) & 1) * 8;
        aTerm[mt] = (uint32_t)(row * 128);
        aXor[mt]  = (uint32_t)((row & 7) << 4);
    }
    const uint32_t aCSel = ((lane >> 4) & 1) * 16;
    uint32_t bTerm[2], bXor[2];
#pragma unroll
    for (int np = 0; np < 2; np++) {
        int row = wn * 32 + np * 16 + (lane & 7) + ((lane >> 4) & 1) * 8;
        bTerm[np] = (uint32_t)(row * 128);
        bXor[np]  = (uint32_t)((row & 7) << 4);
    }
    const uint32_t bCSel = ((lane >> 3) & 1) * 16;

    float acc[4][4][4];
#pragma unroll
    for (int i = 0; i < 4; i++)
#pragma unroll
        for (int j = 0; j < 4; j++)
#pragma unroll
            for (int k = 0; k < 4; k++) acc[i][j][k] = 0.f;

#define ISSUE(c) do { \
        int _c = (c); \
        int pass = _c / NKC, kc = (_c % NKC) * BK; \
        const __nv_bfloat16* aS = (pass < 2 ? Ah : Al) + kc; \
        const __nv_bfloat16* bS = (pass == 1 ? Bl : Bh) + kc; \
        uint32_t st = sb + (uint32_t)(_c % NS) * STAGE_BYTES; \
        CP_ASYNC16(st + aSw[0], aS + aGo[0]); \
        CP_ASYNC16(st + aSw[1], aS + aGo[1]); \
        CP_ASYNC16(st + aSw[2], aS + aGo[2]); \
        CP_ASYNC16(st + aSw[3], aS + aGo[3]); \
        CP_ASYNC16(st + STAGE_A + bSw[0], bS + bGo[0]); \
        CP_ASYNC16(st + STAGE_A + bSw[1], bS + bGo[1]); \
        asm volatile("cp.async.commit_group;" ::: "memory"); \
    } while (0)

    ISSUE(0);
    ISSUE(1);

    for (int c = 0; c < NCHUNK; c++) {
        // group c must be complete: it is newest only at the final iteration
        if (c + 1 < NCHUNK) asm volatile("cp.async.wait_group 1;" ::: "memory");
        else                asm volatile("cp.async.wait_group 0;" ::: "memory");
        __syncthreads();                       // data visible + stage (c-1)%NS drained
        if (c + 2 < NCHUNK) ISSUE(c + 2);

        uint32_t stA = sb + (uint32_t)(c % NS) * STAGE_BYTES;
        uint32_t stB = stA + STAGE_A;
#pragma unroll
        for (int ks = 0; ks < 4; ks++) {
            uint32_t a[4][4], bqr[2][4];
            const uint32_t kb = (uint32_t)(ks * 32);
#pragma unroll
            for (int mt = 0; mt < 4; mt++)
                ldsm_x4(a[mt], stA + aTerm[mt] + ((kb + aCSel) ^ aXor[mt]));
#pragma unroll
            for (int np = 0; np < 2; np++)
                ldsm_x4(bqr[np], stB + bTerm[np] + ((kb + bCSel) ^ bXor[np]));
#pragma unroll
            for (int mt = 0; mt < 4; mt++) {
#pragma unroll
                for (int nt = 0; nt < 4; nt++)
                    mma_bf16(acc[mt][nt], a[mt], &bqr[nt >> 1][(nt & 1) * 2]);
            }
        }
    }
#undef ISSUE

    // ---- epilogue: add bias, store fp32 logits ----
    float* out = g_logits + outOff;
    const int rbase = m0 + wm * 64 + (lane >> 2);
    const int cbase = nloc0 + wn * 32 + (lane & 3) * 2;
#pragma unroll
    for (int mt = 0; mt < 4; mt++) {
#pragma unroll
        for (int nt = 0; nt < 4; nt++) {
            int col = cbase + nt * 8;
            if (col < N) {
                float bx = bias[col], by = bias[col + 1];
                int r0 = rbase + mt * 16;
                float2 v0 = { acc[mt][nt][0] + bx, acc[mt][nt][1] + by };
                float2 v1 = { acc[mt][nt][2] + bx, acc[mt][nt][3] + by };
                *(float2*)&out[(size_t)r0 * N + col]       = v0;
                *(float2*)&out[(size_t)(r0 + 8) * N + col] = v1;
            }
        }
    }
}

// ============================================================
// Fused tail: per row b — 3 LSEs (dual-pipe exp) + NLL +
// hierarchical argmax + acc bins. All logits staged in smem.
// ============================================================
#define TAIL_SMEM ((NC + NM + NF) * 4)

__global__ __launch_bounds__(256)
void k_tail(const float* __restrict__ labels,
            const float* __restrict__ fpart,
            const int*   __restrict__ fparents)
{
    extern __shared__ float sh[];
    float* sC = sh;
    float* sM = sh + NC;
    float* sF = sh + NC + NM;
    __shared__ float rf[9];
    __shared__ int   ri[8];

    int b = blockIdx.x, tid = threadIdx.x;
    int lane = tid & 31, wid = tid >> 5;
    const float* Cv = g_logits + OFF_C + (size_t)b * NC;
    const float* Mv = g_logits + OFF_M + (size_t)b * NM;
    const float* Fv = g_logits + OFF_F + (size_t)b * NF;

    for (int i = tid; i < NC; i += 256) sC[i] = Cv[i];
    for (int i = tid; i < NM; i += 256) sM[i] = Mv[i];
    for (int i = tid; i < NF; i += 256) sF[i] = Fv[i];
    __syncthreads();

    float lse[3];
#pragma unroll
    for (int h = 0; h < 3; h++) {
        const float* v = (h == 0) ? sC : (h == 1) ? sM : sF;
        const int    n = (h == 0) ? NC : (h == 1) ? NM : NF;
        // max
        float m = -3.402823466e38f;
        for (int i = tid; i < n; i += 256) m = fmaxf(m, v[i]);
#pragma unroll
        for (int o = 16; o > 0; o >>= 1)
            m = fmaxf(m, __shfl_xor_sync(0xffffffffu, m, o));
        if (lane == 0) rf[wid] = m;
        __syncthreads();
        if (tid == 0) {
            float mm = rf[0];
#pragma unroll
            for (int j = 1; j < 8; j++) mm = fmaxf(mm, rf[j]);
            rf[8] = mm;
        }
        __syncthreads();
        m = rf[8];
        // sum of exp: alternate MUFU / fma-pipe
        float s = 0.f;
        int par = 0;
        for (int i = tid; i < n; i += 256) {
            float x = v[i] - m;
            s += (par ^= 1) ? __expf(x) : exp_fast(x);
        }
#pragma unroll
        for (int o = 16; o > 0; o >>= 1)
            s += __shfl_xor_sync(0xffffffffu, s, o);
        __syncthreads();
        if (lane == 0) rf[wid] = s;
        __syncthreads();
        if (tid == 0) {
            float ss = 0.f;
#pragma unroll
            for (int j = 0; j < 8; j++) ss += rf[j];
            rf[8] = m + logf(ss);
        }
        __syncthreads();
        lse[h] = rf[8];
        __syncthreads();
    }

    // hierarchical argmax over fine classes
    float best = -3.402823466e38f; int bi = 0x7fffffff;
    for (int f = tid; f < NF; f += 256) {
        float sc = sF[f] + sM[fparents[f]] + sC[g_gp[f]];
        if (sc > best) { best = sc; bi = f; }
    }
#pragma unroll
    for (int o = 16; o > 0; o >>= 1) {
        float ob = __shfl_xor_sync(0xffffffffu, best, o);
        int   oi = __shfl_xor_sync(0xffffffffu, bi,   o);
        if (ob > best || (ob == best && oi < bi)) { best = ob; bi = oi; }
    }
    if (lane == 0) { rf[wid] = best; ri[wid] = bi; }
    __syncthreads();

    if (tid == 0) {
        float bb = rf[0]; int pp = ri[0];
#pragma unroll
        for (int j = 1; j < 8; j++) {
            if (rf[j] > bb || (rf[j] == bb && ri[j] < pp)) { bb = rf[j]; pp = ri[j]; }
        }
        int liC = g_label_idx[b];
        int liM = g_label_idx[B + b];
        int liF = g_label_idx[2 * B + b];
        g_nll[b] = (lse[0] - sC[liC]) + (lse[1] - sM[liM]) + (lse[2] - sF[liF]);

        const float RADF = 0.017453292519943295f;
        float lat1 = labels[b * 2]      * RADF;
        float lon1 = labels[b * 2 + 1]  * RADF;
        float lat2 = fpart[pp * 2]      * RADF;
        float lon2 = fpart[pp * 2 + 1]  * RADF;
        float sdlat = sinf((lat2 - lat1) * 0.5f);
        float sdlon = sinf((lon2 - lon1) * 0.5f);
        float a = sdlat * sdlat + cosf(lat1) * cosf(lat2) * sdlon * sdlon;
        a = fminf(fmaxf(a, 0.f), 1.f);
        float d = 2.0f * 6371.0f * asinf(sqrtf(a));
        if (d <= 1.0f)    atomicAdd(&g_counts[0], 1);
        if (d <= 25.0f)   atomicAdd(&g_counts[1], 1);
        if (d <= 200.0f)  atomicAdd(&g_counts[2], 1);
        if (d <= 750.0f)  atomicAdd(&g_counts[3], 1);
        if (d <= 2500.0f) atomicAdd(&g_counts[4], 1);
    }
}

// ============================================================
// Final deterministic reduction -> out[0]=loss, out[1..5]=acc
// ============================================================
__global__ void k_finalize(float* __restrict__ out)
{
    __shared__ float red[256];
    int tid = threadIdx.x;
    float s = 0.f;
    for (int i = tid; i < B; i += 256) s += g_nll[i];
    red[tid] = s; __syncthreads();
    for (int st = 128; st > 0; st >>= 1) {
        if (tid < st) red[tid] += red[tid + st];
        __syncthreads();
    }
    if (tid == 0) out[0] = red[0] / (float)B;
    if (tid < 5)  out[1 + tid] = (float)g_counts[tid] / (float)B;
}

// ============================================================
extern "C" void kernel_launch(void* const* d_in, const int* in_sizes, int n_in,
                              void* d_out, int out_size)
{
    const float* features = (const float*)d_in[0];
    const float* labels   = (const float*)d_in[1];
    const float* cpart    = (const float*)d_in[2];
    const float* mpart    = (const float*)d_in[3];
    const float* fpart    = (const float*)d_in[4];
    const int*   mparents = (const int*)d_in[5];
    const int*   fparents = (const int*)d_in[6];
    const float* cw = (const float*)d_in[7];
    const float* cb = (const float*)d_in[8];
    const float* mw = (const float*)d_in[9];
    const float* mb = (const float*)d_in[10];
    const float* fw = (const float*)d_in[11];
    const float* fb = (const float*)d_in[12];
    float* out = (float*)d_out;

    static int s_attr_done = 0;
    if (!s_attr_done) {
        cudaFuncSetAttribute(k_mmagemm, cudaFuncAttributeMaxDynamicSharedMemorySize,
                             NS * STAGE_BYTES);
        cudaFuncSetAttribute(k_tail, cudaFuncAttributeMaxDynamicSharedMemorySize,
                             TAIL_SMEM);
        s_attr_done = 1;
    }

    const int half = (B * D) / 2;

    // launch order arranged so ncu (-s 5 -c 1) profiles k_mmagemm (6th launch)
    k_init<<<(NTOT + 255) / 256, 256>>>(labels, cpart, mpart, fpart, mparents, fparents);
    k_convA<<<(half + 255) / 256, 256>>>(features, 0);
    k_convA<<<(half + 255) / 256, 256>>>(features, half);
    k_convW<<<dim3(D / 32, NPTOT / 32), dim3(32, 8)>>>(cw, mw, fw);
    k_labelidx<<<(3 * B + 7) / 8, 256>>>();

    k_mmagemm<<<dim3(B / BM, NPTOT / BN), 512, NS * STAGE_BYTES>>>(cb, mb, fb);

    k_tail<<<B, 256, TAIL_SMEM>>>(labels, fpart, fparents);
    k_finalize<<<1, 256>>>(out);
}

// round 6
// speedup vs baseline: 2.8762x; 1.0633x over previous
#include <cuda_runtime.h>
#include <cuda_bf16.h>
#include <math.h>
#include <stdint.h>

#define B  4096
#define D  1792
#define NC 3000
#define NM 7000
#define NF 13000
#define NTOT (NC + NM + NF)

// padded (tile-128) class counts for the transposed weight buffers
#define NPC 3072
#define NPM 7040
#define NPF 13056
#define SEC_C 0
#define SEC_M 3072
#define SEC_F 10112
#define NPTOT 23168
#define NSTRIP (NPTOT / 128)      // 181
#define NSUB   (NSTRIP * 4)       // 724 sub-strips (one per wn warp)

// sub-strip ranges per head (4 per 128-col strip)
#define SUB_C0 0
#define SUB_CN 96                 // 24 strips * 4
#define SUB_M0 96
#define SUB_MN 220                // 55 strips * 4
#define SUB_F0 316
#define SUB_FN 408                // 102 strips * 4

#define OFF_C ((size_t)0)
#define OFF_M ((size_t)B * NC)
#define OFF_F (OFF_M + (size_t)B * NM)

// ---- device scratch (no runtime allocation allowed) ----
__device__ float         g_logits[(size_t)B * NTOT];   // ~377 MB
__device__ __nv_bfloat16 g_A_hi[(size_t)B * D];
__device__ __nv_bfloat16 g_A_lo[(size_t)B * D];
__device__ __nv_bfloat16 g_Wt_hi[(size_t)NPTOT * D];   // transposed [n][k]
__device__ __nv_bfloat16 g_Wt_lo[(size_t)NPTOT * D];
__device__ float g_pm[(size_t)NSUB * B];               // per-sub-strip row max
__device__ float g_ps[(size_t)NSUB * B];               // per-sub-strip row sumexp
__device__ float g_label_xyz[B * 3];
__device__ float g_part_xyz[NTOT * 3];
__device__ int   g_label_idx[3 * B];
__device__ float g_nll[B];
__device__ int   g_counts[5];

// ============================================================
// helpers
// ============================================================
__device__ __forceinline__ uint32_t smem_to_u32(const void* p) {
    uint32_t a;
    asm("{ .reg .u64 t; cvta.to.shared.u64 t, %1; cvt.u32.u64 %0, t; }"
        : "=r"(a) : "l"(p));
    return a;
}
#define CP_ASYNC16(sm, gp) \
    asm volatile("cp.async.cg.shared.global [%0], [%1], 16;" :: "r"(sm), "l"(gp) : "memory")

__device__ __forceinline__ void ldsm_x4(uint32_t* r, uint32_t addr) {
    asm volatile("ldmatrix.sync.aligned.m8n8.x4.shared.b16 {%0,%1,%2,%3}, [%4];"
        : "=r"(r[0]), "=r"(r[1]), "=r"(r[2]), "=r"(r[3]) : "r"(addr));
}
__device__ __forceinline__ void mma_bf16(float* d, const uint32_t* a, const uint32_t* b) {
    asm volatile("mma.sync.aligned.m16n8k16.row.col.f32.bf16.bf16.f32 "
        "{%0,%1,%2,%3}, {%4,%5,%6,%7}, {%8,%9}, {%0,%1,%2,%3};"
        : "+f"(d[0]), "+f"(d[1]), "+f"(d[2]), "+f"(d[3])
        : "r"(a[0]), "r"(a[1]), "r"(a[2]), "r"(a[3]), "r"(b[0]), "r"(b[1]));
}

// ============================================================
// Kernel: precompute unit vectors, zero counters
// ============================================================
__global__ void k_init(const float* __restrict__ labels,
                       const float* __restrict__ cpart,
                       const float* __restrict__ mpart,
                       const float* __restrict__ fpart)
{
    int t = blockIdx.x * blockDim.x + threadIdx.x;
    const float RADF = 0.017453292519943295f;
    if (t < B) {
        float la = labels[t * 2] * RADF, lo = labels[t * 2 + 1] * RADF;
        float cl = cosf(la);
        g_label_xyz[t * 3 + 0] = cl * cosf(lo);
        g_label_xyz[t * 3 + 1] = cl * sinf(lo);
        g_label_xyz[t * 3 + 2] = sinf(la);
    }
    if (t < NTOT) {
        const float* src;
        if (t < NC)            src = cpart + (size_t)t * 2;
        else if (t < NC + NM)  src = mpart + (size_t)(t - NC) * 2;
        else                   src = fpart + (size_t)(t - NC - NM) * 2;
        float la = src[0] * RADF, lo = src[1] * RADF;
        float cl = cosf(la);
        g_part_xyz[t * 3 + 0] = cl * cosf(lo);
        g_part_xyz[t * 3 + 1] = cl * sinf(lo);
        g_part_xyz[t * 3 + 2] = sinf(la);
    }
    if (t < 5) g_counts[t] = 0;
}

// ============================================================
// Kernel: label index — one WARP per (head, b), shfl argmax reduce
// ============================================================
__global__ __launch_bounds__(256)
void k_labelidx()
{
    int gw = blockIdx.x * 8 + (threadIdx.x >> 5);
    if (gw >= 3 * B) return;
    int lane = threadIdx.x & 31;
    int head = gw >> 12;
    int b    = gw & (B - 1);
    int base, n;
    if (head == 0)      { base = 0;       n = NC; }
    else if (head == 1) { base = NC;      n = NM; }
    else                { base = NC + NM; n = NF; }
    float lx = g_label_xyz[b * 3 + 0];
    float ly = g_label_xyz[b * 3 + 1];
    float lz = g_label_xyz[b * 3 + 2];
    const float* P = g_part_xyz + (size_t)base * 3;
    float best = -2.0f; int bi = 0x7fffffff;
    for (int i = lane; i < n; i += 32) {
        float d = lx * P[i * 3] + ly * P[i * 3 + 1] + lz * P[i * 3 + 2];
        if (d > best || (d == best && i < bi)) { best = d; bi = i; }
    }
#pragma unroll
    for (int off = 16; off > 0; off >>= 1) {
        float ob = __shfl_down_sync(0xffffffffu, best, off);
        int   oi = __shfl_down_sync(0xffffffffu, bi,   off);
        if (ob > best || (ob == best && oi < bi)) { best = ob; bi = oi; }
    }
    if (lane == 0) g_label_idx[head * B + b] = bi;
}

// ============================================================
// Kernel: convert features -> bf16 hi/lo (launched twice, half each)
// ============================================================
__global__ void k_convA(const float* __restrict__ A, int off)
{
    int t = off + blockIdx.x * blockDim.x + threadIdx.x;
    if (t >= B * D) return;
    float v = A[t];
    __nv_bfloat16 h = __float2bfloat16(v);
    __nv_bfloat16 l = __float2bfloat16(v - __bfloat162float(h));
    g_A_hi[t] = h;
    g_A_lo[t] = l;
}

// ============================================================
// Kernel: fused transpose+convert for ALL heads:
// W [D][N] -> Wt [NPTOT][D] bf16 hi/lo (zero pad)
// ============================================================
__global__ void k_convW(const float* __restrict__ cw,
                        const float* __restrict__ mw,
                        const float* __restrict__ fw)
{
    __shared__ float t[32][33];
    int k0 = blockIdx.x * 32;
    int ng0 = blockIdx.y * 32;
    const float* W; int N, sec;
    if (ng0 < SEC_M)      { W = cw; N = NC; sec = SEC_C; }
    else if (ng0 < SEC_F) { W = mw; N = NM; sec = SEC_M; }
    else                  { W = fw; N = NF; sec = SEC_F; }
    int n0 = ng0 - sec;
#pragma unroll
    for (int j = 0; j < 32; j += 8) {
        int k = k0 + threadIdx.y + j;
        int n = n0 + threadIdx.x;
        t[threadIdx.y + j][threadIdx.x] = (n < N) ? W[(size_t)k * N + n] : 0.f;
    }
    __syncthreads();
#pragma unroll
    for (int j = 0; j < 32; j += 8) {
        int n = ng0 + threadIdx.y + j;
        int k = k0 + threadIdx.x;
        float v = t[threadIdx.x][threadIdx.y + j];
        __nv_bfloat16 h = __float2bfloat16(v);
        __nv_bfloat16 l = __float2bfloat16(v - __bfloat162float(h));
        size_t o = (size_t)n * D + k;
        g_Wt_hi[o] = h;
        g_Wt_lo[o] = l;
    }
}

// ============================================================
// Fused bf16x3 GEMM via mma.sync + in-epilogue per-SUB-strip LSE partials.
// 256x128 tile, BK=64, 3-stage cp.async pipe, ONE sync per chunk.
// ============================================================
#define BM 256
#define BN 128
#define BK 64
#define NS 3
#define STAGE_A 32768
#define STAGE_BYTES 49152
#define NKC (D / BK)           // 28
#define NCHUNK (3 * NKC)       // 84

__global__ __launch_bounds__(512, 1)
void k_mmagemm(const float* __restrict__ cb, const float* __restrict__ mb,
               const float* __restrict__ fb)
{
    extern __shared__ __align__(1024) char smem[];
    uint32_t sb = smem_to_u32(smem);
    const int tid  = threadIdx.x;
    const int wid  = tid >> 5;
    const int lane = tid & 31;
    const int wm   = wid >> 2;
    const int wn   = wid & 3;
    const int m0   = blockIdx.x * BM;
    const int n0   = blockIdx.y * BN;

    int N, sec; size_t outOff; const float* bias;
    if (n0 < SEC_M)      { N = NC; sec = SEC_C; outOff = OFF_C; bias = cb; }
    else if (n0 < SEC_F) { N = NM; sec = SEC_M; outOff = OFF_M; bias = mb; }
    else                 { N = NF; sec = SEC_F; outOff = OFF_F; bias = fb; }
    const int nloc0 = n0 - sec;

    uint32_t aSw[4]; size_t aGo[4];
#pragma unroll
    for (int i = 0; i < 4; i++) {
        int idx = tid + i * 512;
        int row = idx >> 3, seg = idx & 7;
        aSw[i] = (uint32_t)(row * 128 + ((seg * 16) ^ ((row & 7) << 4)));
        aGo[i] = (size_t)row * D + seg * 8;
    }
    uint32_t bSw[2]; size_t bGo[2];
#pragma unroll
    for (int i = 0; i < 2; i++) {
        int idx = tid + i * 512;
        int row = idx >> 3, seg = idx & 7;
        bSw[i] = (uint32_t)(row * 128 + ((seg * 16) ^ ((row & 7) << 4)));
        bGo[i] = (size_t)row * D + seg * 8;
    }
    const __nv_bfloat16* Ah = g_A_hi + (size_t)m0 * D;
    const __nv_bfloat16* Al = g_A_lo + (size_t)m0 * D;
    const __nv_bfloat16* Bh = g_Wt_hi + (size_t)n0 * D;
    const __nv_bfloat16* Bl = g_Wt_lo + (size_t)n0 * D;

    uint32_t aTerm[4], aXor[4];
#pragma unroll
    for (int mt = 0; mt < 4; mt++) {
        int row = wm * 64 + mt * 16 + (lane & 7) + ((lane >> 3) & 1) * 8;
        aTerm[mt] = (uint32_t)(row * 128);
        aXor[mt]  = (uint32_t)((row & 7) << 4);
    }
    const uint32_t aCSel = ((lane >> 4) & 1) * 16;
    uint32_t bTerm[2], bXor[2];
#pragma unroll
    for (int np = 0; np < 2; np++) {
        int row = wn * 32 + np * 16 + (lane & 7) + ((lane >> 4) & 1) * 8;
        bTerm[np] = (uint32_t)(row * 128);
        bXor[np]  = (uint32_t)((row & 7) << 4);
    }
    const uint32_t bCSel = ((lane >> 3) & 1) * 16;

    float acc[4][4][4];
#pragma unroll
    for (int i = 0; i < 4; i++)
#pragma unroll
        for (int j = 0; j < 4; j++)
#pragma unroll
            for (int k = 0; k < 4; k++) acc[i][j][k] = 0.f;

#define ISSUE(c) do { \
        int _c = (c); \
        int pass = _c / NKC, kc = (_c % NKC) * BK; \
        const __nv_bfloat16* aS = (pass < 2 ? Ah : Al) + kc; \
        const __nv_bfloat16* bS = (pass == 1 ? Bl : Bh) + kc; \
        uint32_t st = sb + (uint32_t)(_c % NS) * STAGE_BYTES; \
        CP_ASYNC16(st + aSw[0], aS + aGo[0]); \
        CP_ASYNC16(st + aSw[1], aS + aGo[1]); \
        CP_ASYNC16(st + aSw[2], aS + aGo[2]); \
        CP_ASYNC16(st + aSw[3], aS + aGo[3]); \
        CP_ASYNC16(st + STAGE_A + bSw[0], bS + bGo[0]); \
        CP_ASYNC16(st + STAGE_A + bSw[1], bS + bGo[1]); \
        asm volatile("cp.async.commit_group;" ::: "memory"); \
    } while (0)

    ISSUE(0);
    ISSUE(1);

    for (int c = 0; c < NCHUNK; c++) {
        if (c + 1 < NCHUNK) asm volatile("cp.async.wait_group 1;" ::: "memory");
        else                asm volatile("cp.async.wait_group 0;" ::: "memory");
        __syncthreads();
        if (c + 2 < NCHUNK) ISSUE(c + 2);

        uint32_t stA = sb + (uint32_t)(c % NS) * STAGE_BYTES;
        uint32_t stB = stA + STAGE_A;
#pragma unroll
        for (int ks = 0; ks < 4; ks++) {
            uint32_t a[4][4], bqr[2][4];
            const uint32_t kb = (uint32_t)(ks * 32);
#pragma unroll
            for (int mt = 0; mt < 4; mt++)
                ldsm_x4(a[mt], stA + aTerm[mt] + ((kb + aCSel) ^ aXor[mt]));
#pragma unroll
            for (int np = 0; np < 2; np++)
                ldsm_x4(bqr[np], stB + bTerm[np] + ((kb + bCSel) ^ bXor[np]));
#pragma unroll
            for (int mt = 0; mt < 4; mt++) {
#pragma unroll
                for (int nt = 0; nt < 4; nt++)
                    mma_bf16(acc[mt][nt], a[mt], &bqr[nt >> 1][(nt & 1) * 2]);
            }
        }
    }
#undef ISSUE

    // ---- epilogue: bias + store logits + per-SUB-strip LSE partials ----
    // each wn warp owns 32 columns -> its OWN sub-strip slot (no cross-warp race)
    float* out = g_logits + outOff;
    const int sub = blockIdx.y * 4 + wn;
    const int rbase = m0 + wm * 64 + (lane >> 2);
    const int cbase = nloc0 + wn * 32 + (lane & 3) * 2;
#pragma unroll
    for (int mt = 0; mt < 4; mt++) {
        int r0 = rbase + mt * 16;
        float v0[8], v1[8];
#pragma unroll
        for (int nt = 0; nt < 4; nt++) {
            int col = cbase + nt * 8;
            bool ok = (col < N);
            float bx = 0.f, by = 0.f;
            if (ok) { bx = bias[col]; by = bias[col + 1]; }
            float a0 = acc[mt][nt][0] + bx;
            float a1 = acc[mt][nt][1] + by;
            float a2 = acc[mt][nt][2] + bx;
            float a3 = acc[mt][nt][3] + by;
            if (ok) {
                float2 w0 = { a0, a1 }, w1 = { a2, a3 };
                *(float2*)&out[(size_t)r0 * N + col]       = w0;
                *(float2*)&out[(size_t)(r0 + 8) * N + col] = w1;
            }
            v0[nt * 2 + 0] = ok ? a0 : -1e30f;
            v0[nt * 2 + 1] = ok ? a1 : -1e30f;
            v1[nt * 2 + 0] = ok ? a2 : -1e30f;
            v1[nt * 2 + 1] = ok ? a3 : -1e30f;
        }
        float m0v = v0[0], m1v = v1[0];
#pragma unroll
        for (int j = 1; j < 8; j++) { m0v = fmaxf(m0v, v0[j]); m1v = fmaxf(m1v, v1[j]); }
#pragma unroll
        for (int o = 1; o <= 2; o <<= 1) {
            m0v = fmaxf(m0v, __shfl_xor_sync(0xffffffffu, m0v, o));
            m1v = fmaxf(m1v, __shfl_xor_sync(0xffffffffu, m1v, o));
        }
        float s0 = 0.f, s1 = 0.f;
#pragma unroll
        for (int j = 0; j < 8; j++) {
            s0 += __expf(v0[j] - m0v);
            s1 += __expf(v1[j] - m1v);
        }
#pragma unroll
        for (int o = 1; o <= 2; o <<= 1) {
            s0 += __shfl_xor_sync(0xffffffffu, s0, o);
            s1 += __shfl_xor_sync(0xffffffffu, s1, o);
        }
        if ((lane & 3) == 0) {
            g_pm[(size_t)sub * B + r0]     = m0v;
            g_ps[(size_t)sub * B + r0]     = s0;
            g_pm[(size_t)sub * B + r0 + 8] = m1v;
            g_ps[(size_t)sub * B + r0 + 8] = s1;
        }
    }
}

// ============================================================
// Tail: per row b — combine LSE partials (two-pass exact rescale),
// NLL, hierarchical argmax via t[m]=Mv[m]+sC[mp[m]], acc bins.
// ============================================================
#define TAIL_SMEM ((NC + NM) * 4)

__global__ __launch_bounds__(256)
void k_tail(const float* __restrict__ labels,
            const float* __restrict__ fpart,
            const int*   __restrict__ fparents,
            const int*   __restrict__ mparents)
{
    extern __shared__ float sh[];
    float* sC = sh;          // NC
    float* tM = sh + NC;     // NM
    __shared__ float lseS[3];
    __shared__ float rf[8];
    __shared__ int   ri[8];

    int b = blockIdx.x, tid = threadIdx.x;
    int lane = tid & 31, wid = tid >> 5;
    const float* Cv = g_logits + OFF_C + (size_t)b * NC;
    const float* Mv = g_logits + OFF_M + (size_t)b * NM;
    const float* Fv = g_logits + OFF_F + (size_t)b * NF;

    for (int i = tid; i < NC; i += 256) sC[i] = Cv[i];

    // warps 0..2: combine per-sub-strip LSE partials for head wid (2-pass)
    if (wid < 3) {
        int base = (wid == 0) ? SUB_C0 : (wid == 1) ? SUB_M0 : SUB_F0;
        int cnt  = (wid == 0) ? SUB_CN : (wid == 1) ? SUB_MN : SUB_FN;
        float m = -3.402823466e38f;
        for (int i = lane; i < cnt; i += 32)
            m = fmaxf(m, g_pm[(size_t)(base + i) * B + b]);
#pragma unroll
        for (int o = 16; o > 0; o >>= 1)
            m = fmaxf(m, __shfl_xor_sync(0xffffffffu, m, o));
        float s = 0.f;
        for (int i = lane; i < cnt; i += 32)
            s += g_ps[(size_t)(base + i) * B + b] *
                 __expf(g_pm[(size_t)(base + i) * B + b] - m);
#pragma unroll
        for (int o = 16; o > 0; o >>= 1)
            s += __shfl_xor_sync(0xffffffffu, s, o);
        if (lane == 0) lseS[wid] = m + logf(s);
    }
    __syncthreads();

    // t[m] = Mv[m] + sC[mparents[m]]
    for (int i = tid; i < NM; i += 256) tM[i] = Mv[i] + sC[mparents[i]];
    __syncthreads();

    // hierarchical argmax over fine classes
    float best = -3.402823466e38f; int bi = 0x7fffffff;
    for (int f = tid; f < NF; f += 256) {
        float sc = Fv[f] + tM[fparents[f]];
        if (sc > best) { best = sc; bi = f; }
    }
#pragma unroll
    for (int o = 16; o > 0; o >>= 1) {
        float ob = __shfl_xor_sync(0xffffffffu, best, o);
        int   oi = __shfl_xor_sync(0xffffffffu, bi,   o);
        if (ob > best || (ob == best && oi < bi)) { best = ob; bi = oi; }
    }
    if (lane == 0) { rf[wid] = best; ri[wid] = bi; }
    __syncthreads();

    if (tid == 0) {
        float bb = rf[0]; int pp = ri[0];
#pragma unroll
        for (int j = 1; j < 8; j++) {
            if (rf[j] > bb || (rf[j] == bb && ri[j] < pp)) { bb = rf[j]; pp = ri[j]; }
        }
        int liC = g_label_idx[b];
        int liM = g_label_idx[B + b];
        int liF = g_label_idx[2 * B + b];
        g_nll[b] = (lseS[0] - sC[liC]) + (lseS[1] - Mv[liM]) + (lseS[2] - Fv[liF]);

        const float RADF = 0.017453292519943295f;
        float lat1 = labels[b * 2]      * RADF;
        float lon1 = labels[b * 2 + 1]  * RADF;
        float lat2 = fpart[pp * 2]      * RADF;
        float lon2 = fpart[pp * 2 + 1]  * RADF;
        float sdlat = sinf((lat2 - lat1) * 0.5f);
        float sdlon = sinf((lon2 - lon1) * 0.5f);
        float a = sdlat * sdlat + cosf(lat1) * cosf(lat2) * sdlon * sdlon;
        a = fminf(fmaxf(a, 0.f), 1.f);
        float d = 2.0f * 6371.0f * asinf(sqrtf(a));
        if (d <= 1.0f)    atomicAdd(&g_counts[0], 1);
        if (d <= 25.0f)   atomicAdd(&g_counts[1], 1);
        if (d <= 200.0f)  atomicAdd(&g_counts[2], 1);
        if (d <= 750.0f)  atomicAdd(&g_counts[3], 1);
        if (d <= 2500.0f) atomicAdd(&g_counts[4], 1);
    }
}

// ============================================================
// Final deterministic reduction -> out[0]=loss, out[1..5]=acc
// ============================================================
__global__ void k_finalize(float* __restrict__ out)
{
    __shared__ float red[256];
    int tid = threadIdx.x;
    float s = 0.f;
    for (int i = tid; i < B; i += 256) s += g_nll[i];
    red[tid] = s; __syncthreads();
    for (int st = 128; st > 0; st >>= 1) {
        if (tid < st) red[tid] += red[tid + st];
        __syncthreads();
    }
    if (tid == 0) out[0] = red[0] / (float)B;
    if (tid < 5)  out[1 + tid] = (float)g_counts[tid] / (float)B;
}

// ============================================================
extern "C" void kernel_launch(void* const* d_in, const int* in_sizes, int n_in,
                              void* d_out, int out_size)
{
    const float* features = (const float*)d_in[0];
    const float* labels   = (const float*)d_in[1];
    const float* cpart    = (const float*)d_in[2];
    const float* mpart    = (const float*)d_in[3];
    const float* fpart    = (const float*)d_in[4];
    const int*   mparents = (const int*)d_in[5];
    const int*   fparents = (const int*)d_in[6];
    const float* cw = (const float*)d_in[7];
    const float* cb = (const float*)d_in[8];
    const float* mw = (const float*)d_in[9];
    const float* mb = (const float*)d_in[10];
    const float* fw = (const float*)d_in[11];
    const float* fb = (const float*)d_in[12];
    float* out = (float*)d_out;

    static int s_attr_done = 0;
    if (!s_attr_done) {
        cudaFuncSetAttribute(k_mmagemm, cudaFuncAttributeMaxDynamicSharedMemorySize,
                             NS * STAGE_BYTES);
        cudaFuncSetAttribute(k_tail, cudaFuncAttributeMaxDynamicSharedMemorySize,
                             TAIL_SMEM);
        s_attr_done = 1;
    }

    const int half = (B * D) / 2;

    k_init<<<(NTOT + 255) / 256, 256>>>(labels, cpart, mpart, fpart);
    k_convA<<<(half + 255) / 256, 256>>>(features, 0);
    k_convA<<<(half + 255) / 256, 256>>>(features, half);
    k_convW<<<dim3(D / 32, NPTOT / 32), dim3(32, 8)>>>(cw, mw, fw);
    k_labelidx<<<(3 * B + 7) / 8, 256>>>();

    k_mmagemm<<<dim3(B / BM, NPTOT / BN), 512, NS * STAGE_BYTES>>>(cb, mb, fb);

    k_tail<<<B, 256, TAIL_SMEM>>>(labels, fpart, fparents, mparents);
    k_finalize<<<1, 256>>>(out);
}

// round 7
// speedup vs baseline: 3.2959x; 1.1459x over previous
#include <cuda_runtime.h>
#include <cuda_bf16.h>
#include <math.h>
#include <stdint.h>

#define B  4096
#define D  1792
#define NC 3000
#define NM 7000
#define NF 13000
#define NTOT (NC + NM + NF)

// padded (tile-256) class counts for the transposed weight buffers
#define NPC 3072
#define NPM 7168
#define NPF 13056
#define SEC_C 0
#define SEC_M 3072
#define SEC_F 10240
#define NPTOT 23296
#define NSTRIP (NPTOT / 256)      // 91
#define NSUB   (NSTRIP * 4)       // 364 sub-strips of 64 cols

// sub-strip ranges per head (4 per 256-col strip)
#define SUB_C0 0
#define SUB_CN 48                 // 12 strips * 4
#define SUB_M0 48
#define SUB_MN 112                // 28 strips * 4
#define SUB_F0 160
#define SUB_FN 204                // 51 strips * 4

#define OFF_C ((size_t)0)
#define OFF_M ((size_t)B * NC)
#define OFF_F (OFF_M + (size_t)B * NM)

// ---- device scratch (no runtime allocation allowed) ----
__device__ float         g_logits[(size_t)B * NTOT];   // ~377 MB
__device__ __nv_bfloat16 g_A_hi[(size_t)B * D];
__device__ __nv_bfloat16 g_A_lo[(size_t)B * D];
__device__ __nv_bfloat16 g_Wt_hi[(size_t)NPTOT * D];   // transposed [n][k]
__device__ __nv_bfloat16 g_Wt_lo[(size_t)NPTOT * D];
__device__ float g_pm[(size_t)NSUB * B];               // per-sub-strip row max
__device__ float g_ps[(size_t)NSUB * B];               // per-sub-strip row sumexp
__device__ float g_label_xyz[B * 3];
__device__ float g_part_xyz[NTOT * 3];
__device__ int   g_label_idx[3 * B];
__device__ float g_nll[B];
__device__ int   g_counts[5];

// ============================================================
// helpers
// ============================================================
__device__ __forceinline__ uint32_t smem_to_u32(const void* p) {
    uint32_t a;
    asm("{ .reg .u64 t; cvta.to.shared.u64 t, %1; cvt.u32.u64 %0, t; }"
        : "=r"(a) : "l"(p));
    return a;
}
#define CP_ASYNC16(sm, gp) \
    asm volatile("cp.async.cg.shared.global [%0], [%1], 16;" :: "r"(sm), "l"(gp) : "memory")

__device__ __forceinline__ void ldsm_x4(uint32_t* r, uint32_t addr) {
    asm volatile("ldmatrix.sync.aligned.m8n8.x4.shared.b16 {%0,%1,%2,%3}, [%4];"
        : "=r"(r[0]), "=r"(r[1]), "=r"(r[2]), "=r"(r[3]) : "r"(addr));
}
__device__ __forceinline__ void mma_bf16(float* d, const uint32_t* a, const uint32_t* b) {
    asm volatile("mma.sync.aligned.m16n8k16.row.col.f32.bf16.bf16.f32 "
        "{%0,%1,%2,%3}, {%4,%5,%6,%7}, {%8,%9}, {%0,%1,%2,%3};"
        : "+f"(d[0]), "+f"(d[1]), "+f"(d[2]), "+f"(d[3])
        : "r"(a[0]), "r"(a[1]), "r"(a[2]), "r"(a[3]), "r"(b[0]), "r"(b[1]));
}

// ============================================================
// Kernel: precompute unit vectors, zero counters
// ============================================================
__global__ void k_init(const float* __restrict__ labels,
                       const float* __restrict__ cpart,
                       const float* __restrict__ mpart,
                       const float* __restrict__ fpart)
{
    int t = blockIdx.x * blockDim.x + threadIdx.x;
    const float RADF = 0.017453292519943295f;
    if (t < B) {
        float la = labels[t * 2] * RADF, lo = labels[t * 2 + 1] * RADF;
        float cl = cosf(la);
        g_label_xyz[t * 3 + 0] = cl * cosf(lo);
        g_label_xyz[t * 3 + 1] = cl * sinf(lo);
        g_label_xyz[t * 3 + 2] = sinf(la);
    }
    if (t < NTOT) {
        const float* src;
        if (t < NC)            src = cpart + (size_t)t * 2;
        else if (t < NC + NM)  src = mpart + (size_t)(t - NC) * 2;
        else                   src = fpart + (size_t)(t - NC - NM) * 2;
        float la = src[0] * RADF, lo = src[1] * RADF;
        float cl = cosf(la);
        g_part_xyz[t * 3 + 0] = cl * cosf(lo);
        g_part_xyz[t * 3 + 1] = cl * sinf(lo);
        g_part_xyz[t * 3 + 2] = sinf(la);
    }
    if (t < 5) g_counts[t] = 0;
}

// ============================================================
// Kernel: label index — one WARP per (head, b), shfl argmax reduce
// ============================================================
__global__ __launch_bounds__(256)
void k_labelidx()
{
    int gw = blockIdx.x * 8 + (threadIdx.x >> 5);
    if (gw >= 3 * B) return;
    int lane = threadIdx.x & 31;
    int head = gw >> 12;
    int b    = gw & (B - 1);
    int base, n;
    if (head == 0)      { base = 0;       n = NC; }
    else if (head == 1) { base = NC;      n = NM; }
    else                { base = NC + NM; n = NF; }
    float lx = g_label_xyz[b * 3 + 0];
    float ly = g_label_xyz[b * 3 + 1];
    float lz = g_label_xyz[b * 3 + 2];
    const float* P = g_part_xyz + (size_t)base * 3;
    float best = -2.0f; int bi = 0x7fffffff;
    for (int i = lane; i < n; i += 32) {
        float d = lx * P[i * 3] + ly * P[i * 3 + 1] + lz * P[i * 3 + 2];
        if (d > best || (d == best && i < bi)) { best = d; bi = i; }
    }
#pragma unroll
    for (int off = 16; off > 0; off >>= 1) {
        float ob = __shfl_down_sync(0xffffffffu, best, off);
        int   oi = __shfl_down_sync(0xffffffffu, bi,   off);
        if (ob > best || (ob == best && oi < bi)) { best = ob; bi = oi; }
    }
    if (lane == 0) g_label_idx[head * B + b] = bi;
}

// ============================================================
// Kernel: convert features -> bf16 hi/lo (launched twice, half each)
// ============================================================
__global__ void k_convA(const float* __restrict__ A, int off)
{
    int t = off + blockIdx.x * blockDim.x + threadIdx.x;
    if (t >= B * D) return;
    float v = A[t];
    __nv_bfloat16 h = __float2bfloat16(v);
    __nv_bfloat16 l = __float2bfloat16(v - __bfloat162float(h));
    g_A_hi[t] = h;
    g_A_lo[t] = l;
}

// ============================================================
// Kernel: fused transpose+convert for ALL heads:
// W [D][N] -> Wt [NPTOT][D] bf16 hi/lo (zero pad)
// ============================================================
__global__ void k_convW(const float* __restrict__ cw,
                        const float* __restrict__ mw,
                        const float* __restrict__ fw)
{
    __shared__ float t[32][33];
    int k0 = blockIdx.x * 32;
    int ng0 = blockIdx.y * 32;
    const float* W; int N, sec;
    if (ng0 < SEC_M)      { W = cw; N = NC; sec = SEC_C; }
    else if (ng0 < SEC_F) { W = mw; N = NM; sec = SEC_M; }
    else                  { W = fw; N = NF; sec = SEC_F; }
    int n0 = ng0 - sec;
#pragma unroll
    for (int j = 0; j < 32; j += 8) {
        int k = k0 + threadIdx.y + j;
        int n = n0 + threadIdx.x;
        t[threadIdx.y + j][threadIdx.x] = (n < N) ? W[(size_t)k * N + n] : 0.f;
    }
    __syncthreads();
#pragma unroll
    for (int j = 0; j < 32; j += 8) {
        int n = ng0 + threadIdx.y + j;
        int k = k0 + threadIdx.x;
        float v = t[threadIdx.x][threadIdx.y + j];
        __nv_bfloat16 h = __float2bfloat16(v);
        __nv_bfloat16 l = __float2bfloat16(v - __bfloat162float(h));
        size_t o = (size_t)n * D + k;
        g_Wt_hi[o] = h;
        g_Wt_lo[o] = l;
    }
}

// ============================================================
// Merged-pass bf16x3 GEMM: per K-chunk compute AhBh + AhBl + AlBh
// from one stage holding Ah,Al,Bh,Bl. 128x256 tile, warp tile 64x64,
// 256 threads, 2-stage cp.async pipe. In-epilogue sub-strip LSE.
// ============================================================
#define BM 128
#define BN 256
#define BK 64
#define ST_AH 0
#define ST_AL 16384
#define ST_BH 32768
#define ST_BL 65536
#define STAGE_BYTES 98304
#define GEMM_SMEM (2 * STAGE_BYTES)
#define NKC (D / BK)              // 28

__global__ __launch_bounds__(256, 1)
void k_mmagemm(const float* __restrict__ cb, const float* __restrict__ mb,
               const float* __restrict__ fb)
{
    extern __shared__ __align__(1024) char smem[];
    uint32_t sb = smem_to_u32(smem);
    const int tid  = threadIdx.x;
    const int wid  = tid >> 5;
    const int lane = tid & 31;
    const int wm   = wid >> 2;     // 0..1
    const int wn   = wid & 3;      // 0..3
    const int m0   = blockIdx.x * BM;
    const int n0   = blockIdx.y * BN;

    int N, sec; size_t outOff; const float* bias;
    if (n0 < SEC_M)      { N = NC; sec = SEC_C; outOff = OFF_C; bias = cb; }
    else if (n0 < SEC_F) { N = NM; sec = SEC_M; outOff = OFF_M; bias = mb; }
    else                 { N = NF; sec = SEC_F; outOff = OFF_F; bias = fb; }
    const int nloc0 = n0 - sec;

    // ---- cp.async addressing: A 4 segs/thread, B 8 segs/thread ----
    uint32_t aSw[4], aGo[4];
#pragma unroll
    for (int i = 0; i < 4; i++) {
        int idx = tid + i * 256;              // 0..1023
        int row = idx >> 3, seg = idx & 7;
        aSw[i] = (uint32_t)(row * 128 + ((seg * 16) ^ ((row & 7) << 4)));
        aGo[i] = (uint32_t)((row * D + seg * 8) * 2);     // byte offset
    }
    uint32_t bSw[8], bGo[8];
#pragma unroll
    for (int i = 0; i < 8; i++) {
        int idx = tid + i * 256;              // 0..2047
        int row = idx >> 3, seg = idx & 7;
        bSw[i] = (uint32_t)(row * 128 + ((seg * 16) ^ ((row & 7) << 4)));
        bGo[i] = (uint32_t)((row * D + seg * 8) * 2);
    }
    const char* Ahp = (const char*)(g_A_hi  + (size_t)m0 * D);
    const char* Alp = (const char*)(g_A_lo  + (size_t)m0 * D);
    const char* Bhp = (const char*)(g_Wt_hi + (size_t)n0 * D);
    const char* Blp = (const char*)(g_Wt_lo + (size_t)n0 * D);

    // ---- ldsm per-lane addressing ----
    uint32_t aTerm[4], aXor[4];
#pragma unroll
    for (int mt = 0; mt < 4; mt++) {
        int row = wm * 64 + mt * 16 + (lane & 7) + ((lane >> 3) & 1) * 8;
        aTerm[mt] = (uint32_t)(row * 128);
        aXor[mt]  = (uint32_t)((row & 7) << 4);
    }
    const uint32_t aCSel = ((lane >> 4) & 1) * 16;
    uint32_t bTerm[4], bXor[4];
#pragma unroll
    for (int np = 0; np < 4; np++) {
        int row = wn * 64 + np * 16 + (lane & 7) + ((lane >> 4) & 1) * 8;
        bTerm[np] = (uint32_t)(row * 128);
        bXor[np]  = (uint32_t)((row & 7) << 4);
    }
    const uint32_t bCSel = ((lane >> 3) & 1) * 16;

    float acc[4][8][4];
#pragma unroll
    for (int i = 0; i < 4; i++)
#pragma unroll
        for (int j = 0; j < 8; j++)
#pragma unroll
            for (int k = 0; k < 4; k++) acc[i][j][k] = 0.f;

#define ISSUE(c) do { \
        int _c = (c); \
        uint32_t kb2 = (uint32_t)(_c * BK * 2); \
        uint32_t st = sb + (uint32_t)(_c & 1) * STAGE_BYTES; \
        _Pragma("unroll") \
        for (int i = 0; i < 4; i++) { \
            CP_ASYNC16(st + ST_AH + aSw[i], Ahp + kb2 + aGo[i]); \
            CP_ASYNC16(st + ST_AL + aSw[i], Alp + kb2 + aGo[i]); \
        } \
        _Pragma("unroll") \
        for (int i = 0; i < 8; i++) { \
            CP_ASYNC16(st + ST_BH + bSw[i], Bhp + kb2 + bGo[i]); \
            CP_ASYNC16(st + ST_BL + bSw[i], Blp + kb2 + bGo[i]); \
        } \
        asm volatile("cp.async.commit_group;" ::: "memory"); \
    } while (0)

    ISSUE(0);
    ISSUE(1);

    for (int c = 0; c < NKC; c++) {
        if (c + 1 < NKC) asm volatile("cp.async.wait_group 1;" ::: "memory");
        else             asm volatile("cp.async.wait_group 0;" ::: "memory");
        __syncthreads();
        uint32_t st = sb + (uint32_t)(c & 1) * STAGE_BYTES;
#pragma unroll
        for (int ks = 0; ks < 4; ks++) {
            const uint32_t kb = (uint32_t)(ks * 32);
            uint32_t a[4][4], bh[4][4], bl[4][4];
#pragma unroll
            for (int mt = 0; mt < 4; mt++)
                ldsm_x4(a[mt], st + ST_AH + aTerm[mt] + ((kb + aCSel) ^ aXor[mt]));
#pragma unroll
            for (int np = 0; np < 4; np++)
                ldsm_x4(bh[np], st + ST_BH + bTerm[np] + ((kb + bCSel) ^ bXor[np]));
#pragma unroll
            for (int np = 0; np < 4; np++)
                ldsm_x4(bl[np], st + ST_BL + bTerm[np] + ((kb + bCSel) ^ bXor[np]));
            // Ah * Bh
#pragma unroll
            for (int mt = 0; mt < 4; mt++)
#pragma unroll
                for (int nt = 0; nt < 8; nt++)
                    mma_bf16(acc[mt][nt], a[mt], &bh[nt >> 1][(nt & 1) * 2]);
            // Ah * Bl
#pragma unroll
            for (int mt = 0; mt < 4; mt++)
#pragma unroll
                for (int nt = 0; nt < 8; nt++)
                    mma_bf16(acc[mt][nt], a[mt], &bl[nt >> 1][(nt & 1) * 2]);
            // Al * Bh (reload a-frags from Al region)
#pragma unroll
            for (int mt = 0; mt < 4; mt++)
                ldsm_x4(a[mt], st + ST_AL + aTerm[mt] + ((kb + aCSel) ^ aXor[mt]));
#pragma unroll
            for (int mt = 0; mt < 4; mt++)
#pragma unroll
                for (int nt = 0; nt < 8; nt++)
                    mma_bf16(acc[mt][nt], a[mt], &bh[nt >> 1][(nt & 1) * 2]);
        }
        __syncthreads();
        if (c + 2 < NKC) ISSUE(c + 2);
    }
#undef ISSUE

    // ---- epilogue: bias + store logits + per-sub-strip LSE partials ----
    float* out = g_logits + outOff;
    const int sub = blockIdx.y * 4 + wn;
    const int rbase = m0 + wm * 64 + (lane >> 2);
    const int cb0 = nloc0 + wn * 64 + (lane & 3) * 2;
#pragma unroll
    for (int mt = 0; mt < 4; mt++) {
        int r0 = rbase + mt * 16;
        float v0[16], v1[16];
#pragma unroll
        for (int nt = 0; nt < 8; nt++) {
            int col = cb0 + nt * 8;
            bool ok = (col < N);
            float bx = 0.f, by = 0.f;
            if (ok) { bx = bias[col]; by = bias[col + 1]; }
            float a0 = acc[mt][nt][0] + bx;
            float a1 = acc[mt][nt][1] + by;
            float a2 = acc[mt][nt][2] + bx;
            float a3 = acc[mt][nt][3] + by;
            if (ok) {
                float2 w0 = { a0, a1 }, w1 = { a2, a3 };
                *(float2*)&out[(size_t)r0 * N + col]       = w0;
                *(float2*)&out[(size_t)(r0 + 8) * N + col] = w1;
            }
            v0[nt * 2 + 0] = ok ? a0 : -1e30f;
            v0[nt * 2 + 1] = ok ? a1 : -1e30f;
            v1[nt * 2 + 0] = ok ? a2 : -1e30f;
            v1[nt * 2 + 1] = ok ? a3 : -1e30f;
        }
        float m0v = v0[0], m1v = v1[0];
#pragma unroll
        for (int j = 1; j < 16; j++) { m0v = fmaxf(m0v, v0[j]); m1v = fmaxf(m1v, v1[j]); }
#pragma unroll
        for (int o = 1; o <= 2; o <<= 1) {
            m0v = fmaxf(m0v, __shfl_xor_sync(0xffffffffu, m0v, o));
            m1v = fmaxf(m1v, __shfl_xor_sync(0xffffffffu, m1v, o));
        }
        float s0 = 0.f, s1 = 0.f;
#pragma unroll
        for (int j = 0; j < 16; j++) {
            s0 += __expf(v0[j] - m0v);
            s1 += __expf(v1[j] - m1v);
        }
#pragma unroll
        for (int o = 1; o <= 2; o <<= 1) {
            s0 += __shfl_xor_sync(0xffffffffu, s0, o);
            s1 += __shfl_xor_sync(0xffffffffu, s1, o);
        }
        if ((lane & 3) == 0) {
            g_pm[(size_t)sub * B + r0]     = m0v;
            g_ps[(size_t)sub * B + r0]     = s0;
            g_pm[(size_t)sub * B + r0 + 8] = m1v;
            g_ps[(size_t)sub * B + r0 + 8] = s1;
        }
    }
}

// ============================================================
// Tail: per row b — combine LSE partials (two-pass exact rescale),
// NLL, hierarchical argmax via t[m]=Mv[m]+sC[mp[m]], acc bins.
// ============================================================
#define TAIL_SMEM ((NC + NM) * 4)

__global__ __launch_bounds__(256)
void k_tail(const float* __restrict__ labels,
            const float* __restrict__ fpart,
            const int*   __restrict__ fparents,
            const int*   __restrict__ mparents)
{
    extern __shared__ float sh[];
    float* sC = sh;          // NC
    float* tM = sh + NC;     // NM
    __shared__ float lseS[3];
    __shared__ float rf[8];
    __shared__ int   ri[8];

    int b = blockIdx.x, tid = threadIdx.x;
    int lane = tid & 31, wid = tid >> 5;
    const float* Cv = g_logits + OFF_C + (size_t)b * NC;
    const float* Mv = g_logits + OFF_M + (size_t)b * NM;
    const float* Fv = g_logits + OFF_F + (size_t)b * NF;

    for (int i = tid; i < NC; i += 256) sC[i] = Cv[i];

    // warps 0..2: combine per-sub-strip LSE partials for head wid (2-pass)
    if (wid < 3) {
        int base = (wid == 0) ? SUB_C0 : (wid == 1) ? SUB_M0 : SUB_F0;
        int cnt  = (wid == 0) ? SUB_CN : (wid == 1) ? SUB_MN : SUB_FN;
        float m = -3.402823466e38f;
        for (int i = lane; i < cnt; i += 32)
            m = fmaxf(m, g_pm[(size_t)(base + i) * B + b]);
#pragma unroll
        for (int o = 16; o > 0; o >>= 1)
            m = fmaxf(m, __shfl_xor_sync(0xffffffffu, m, o));
        float s = 0.f;
        for (int i = lane; i < cnt; i += 32)
            s += g_ps[(size_t)(base + i) * B + b] *
                 __expf(g_pm[(size_t)(base + i) * B + b] - m);
#pragma unroll
        for (int o = 16; o > 0; o >>= 1)
            s += __shfl_xor_sync(0xffffffffu, s, o);
        if (lane == 0) lseS[wid] = m + logf(s);
    }
    __syncthreads();

    // t[m] = Mv[m] + sC[mparents[m]]
    for (int i = tid; i < NM; i += 256) tM[i] = Mv[i] + sC[mparents[i]];
    __syncthreads();

    // hierarchical argmax over fine classes
    float best = -3.402823466e38f; int bi = 0x7fffffff;
    for (int f = tid; f < NF; f += 256) {
        float sc = Fv[f] + tM[fparents[f]];
        if (sc > best) { best = sc; bi = f; }
    }
#pragma unroll
    for (int o = 16; o > 0; o >>= 1) {
        float ob = __shfl_xor_sync(0xffffffffu, best, o);
        int   oi = __shfl_xor_sync(0xffffffffu, bi,   o);
        if (ob > best || (ob == best && oi < bi)) { best = ob; bi = oi; }
    }
    if (lane == 0) { rf[wid] = best; ri[wid] = bi; }
    __syncthreads();

    if (tid == 0) {
        float bb = rf[0]; int pp = ri[0];
#pragma unroll
        for (int j = 1; j < 8; j++) {
            if (rf[j] > bb || (rf[j] == bb && ri[j] < pp)) { bb = rf[j]; pp = ri[j]; }
        }
        int liC = g_label_idx[b];
        int liM = g_label_idx[B + b];
        int liF = g_label_idx[2 * B + b];
        g_nll[b] = (lseS[0] - sC[liC]) + (lseS[1] - Mv[liM]) + (lseS[2] - Fv[liF]);

        const float RADF = 0.017453292519943295f;
        float lat1 = labels[b * 2]      * RADF;
        float lon1 = labels[b * 2 + 1]  * RADF;
        float lat2 = fpart[pp * 2]      * RADF;
        float lon2 = fpart[pp * 2 + 1]  * RADF;
        float sdlat = sinf((lat2 - lat1) * 0.5f);
        float sdlon = sinf((lon2 - lon1) * 0.5f);
        float a = sdlat * sdlat + cosf(lat1) * cosf(lat2) * sdlon * sdlon;
        a = fminf(fmaxf(a, 0.f), 1.f);
        float d = 2.0f * 6371.0f * asinf(sqrtf(a));
        if (d <= 1.0f)    atomicAdd(&g_counts[0], 1);
        if (d <= 25.0f)   atomicAdd(&g_counts[1], 1);
        if (d <= 200.0f)  atomicAdd(&g_counts[2], 1);
        if (d <= 750.0f)  atomicAdd(&g_counts[3], 1);
        if (d <= 2500.0f) atomicAdd(&g_counts[4], 1);
    }
}

// ============================================================
// Final deterministic reduction -> out[0]=loss, out[1..5]=acc
// ============================================================
__global__ void k_finalize(float* __restrict__ out)
{
    __shared__ float red[256];
    int tid = threadIdx.x;
    float s = 0.f;
    for (int i = tid; i < B; i += 256) s += g_nll[i];
    red[tid] = s; __syncthreads();
    for (int st = 128; st > 0; st >>= 1) {
        if (tid < st) red[tid] += red[tid + st];
        __syncthreads();
    }
    if (tid == 0) out[0] = red[0] / (float)B;
    if (tid < 5)  out[1 + tid] = (float)g_counts[tid] / (float)B;
}

// ============================================================
extern "C" void kernel_launch(void* const* d_in, const int* in_sizes, int n_in,
                              void* d_out, int out_size)
{
    const float* features = (const float*)d_in[0];
    const float* labels   = (const float*)d_in[1];
    const float* cpart    = (const float*)d_in[2];
    const float* mpart    = (const float*)d_in[3];
    const float* fpart    = (const float*)d_in[4];
    const int*   mparents = (const int*)d_in[5];
    const int*   fparents = (const int*)d_in[6];
    const float* cw = (const float*)d_in[7];
    const float* cb = (const float*)d_in[8];
    const float* mw = (const float*)d_in[9];
    const float* mb = (const float*)d_in[10];
    const float* fw = (const float*)d_in[11];
    const float* fb = (const float*)d_in[12];
    float* out = (float*)d_out;

    static int s_attr_done = 0;
    if (!s_attr_done) {
        cudaFuncSetAttribute(k_mmagemm, cudaFuncAttributeMaxDynamicSharedMemorySize,
                             GEMM_SMEM);
        cudaFuncSetAttribute(k_tail, cudaFuncAttributeMaxDynamicSharedMemorySize,
                             TAIL_SMEM);
        s_attr_done = 1;
    }

    const int half = (B * D) / 2;

    k_init<<<(NTOT + 255) / 256, 256>>>(labels, cpart, mpart, fpart);
    k_convA<<<(half + 255) / 256, 256>>>(features, 0);
    k_convA<<<(half + 255) / 256, 256>>>(features, half);
    k_convW<<<dim3(D / 32, NPTOT / 32), dim3(32, 8)>>>(cw, mw, fw);
    k_labelidx<<<(3 * B + 7) / 8, 256>>>();

    k_mmagemm<<<dim3(B / BM, NPTOT / BN), 256, GEMM_SMEM>>>(cb, mb, fb);

    k_tail<<<B, 256, TAIL_SMEM>>>(labels, fpart, fparents, mparents);
    k_finalize<<<1, 256>>>(out);
}

// round 8
// speedup vs baseline: 3.3025x; 1.0020x over previous
#include <cuda_runtime.h>
#include <cuda_bf16.h>
#include <math.h>
#include <stdint.h>

#define B  4096
#define D  1792
#define NC 3000
#define NM 7000
#define NF 13000
#define NTOT (NC + NM + NF)

// padded (tile-256) class counts for the transposed weight buffers
#define NPC 3072
#define NPM 7168
#define NPF 13056
#define SEC_C 0
#define SEC_M 3072
#define SEC_F 10240
#define NPTOT 23296
#define NSTRIP (NPTOT / 256)      // 91
#define NSUB   (NSTRIP * 4)       // 364 sub-strips of 64 cols

// sub-strip ranges per head (4 per 256-col strip)
#define SUB_C0 0
#define SUB_CN 48                 // 12 strips * 4
#define SUB_M0 48
#define SUB_MN 112                // 28 strips * 4
#define SUB_F0 160
#define SUB_FN 204                // 51 strips * 4

#define OFF_C ((size_t)0)
#define OFF_M ((size_t)B * NC)
#define OFF_F (OFF_M + (size_t)B * NM)

// ---- device scratch (no runtime allocation allowed) ----
__device__ float         g_logits[(size_t)B * NTOT];   // ~377 MB
__device__ __nv_bfloat16 g_A_hi[(size_t)B * D];
__device__ __nv_bfloat16 g_A_lo[(size_t)B * D];
__device__ __nv_bfloat16 g_Wt_hi[(size_t)NPTOT * D];   // transposed [n][k]
__device__ __nv_bfloat16 g_Wt_lo[(size_t)NPTOT * D];
__device__ float g_pm[(size_t)NSUB * B];               // per-sub-strip row max
__device__ float g_ps[(size_t)NSUB * B];               // per-sub-strip row sumexp
__device__ float g_label_xyz[B * 3];
__device__ float g_part_xyz[NTOT * 3];
__device__ int   g_label_idx[3 * B];
__device__ float g_nll[B];
__device__ int   g_counts[5];

// ============================================================
// helpers
// ============================================================
__device__ __forceinline__ uint32_t smem_to_u32(const void* p) {
    uint32_t a;
    asm("{ .reg .u64 t; cvta.to.shared.u64 t, %1; cvt.u32.u64 %0, t; }"
        : "=r"(a) : "l"(p));
    return a;
}
#define CP_ASYNC16(sm, gp) \
    asm volatile("cp.async.cg.shared.global [%0], [%1], 16;" :: "r"(sm), "l"(gp) : "memory")

__device__ __forceinline__ void ldsm_x4(uint32_t* r, uint32_t addr) {
    asm volatile("ldmatrix.sync.aligned.m8n8.x4.shared.b16 {%0,%1,%2,%3}, [%4];"
        : "=r"(r[0]), "=r"(r[1]), "=r"(r[2]), "=r"(r[3]) : "r"(addr));
}
__device__ __forceinline__ void mma_bf16(float* d, const uint32_t* a, const uint32_t* b) {
    asm volatile("mma.sync.aligned.m16n8k16.row.col.f32.bf16.bf16.f32 "
        "{%0,%1,%2,%3}, {%4,%5,%6,%7}, {%8,%9}, {%0,%1,%2,%3};"
        : "+f"(d[0]), "+f"(d[1]), "+f"(d[2]), "+f"(d[3])
        : "r"(a[0]), "r"(a[1]), "r"(a[2]), "r"(a[3]), "r"(b[0]), "r"(b[1]));
}

// ============================================================
// Kernel: precompute unit vectors, zero counters
// ============================================================
__global__ void k_init(const float* __restrict__ labels,
                       const float* __restrict__ cpart,
                       const float* __restrict__ mpart,
                       const float* __restrict__ fpart)
{
    int t = blockIdx.x * blockDim.x + threadIdx.x;
    const float RADF = 0.017453292519943295f;
    if (t < B) {
        float la = labels[t * 2] * RADF, lo = labels[t * 2 + 1] * RADF;
        float cl = cosf(la);
        g_label_xyz[t * 3 + 0] = cl * cosf(lo);
        g_label_xyz[t * 3 + 1] = cl * sinf(lo);
        g_label_xyz[t * 3 + 2] = sinf(la);
    }
    if (t < NTOT) {
        const float* src;
        if (t < NC)            src = cpart + (size_t)t * 2;
        else if (t < NC + NM)  src = mpart + (size_t)(t - NC) * 2;
        else                   src = fpart + (size_t)(t - NC - NM) * 2;
        float la = src[0] * RADF, lo = src[1] * RADF;
        float cl = cosf(la);
        g_part_xyz[t * 3 + 0] = cl * cosf(lo);
        g_part_xyz[t * 3 + 1] = cl * sinf(lo);
        g_part_xyz[t * 3 + 2] = sinf(la);
    }
    if (t < 5) g_counts[t] = 0;
}

// ============================================================
// Kernel: label index — one WARP per (head, b), shfl argmax reduce
// ============================================================
__global__ __launch_bounds__(256)
void k_labelidx()
{
    int gw = blockIdx.x * 8 + (threadIdx.x >> 5);
    if (gw >= 3 * B) return;
    int lane = threadIdx.x & 31;
    int head = gw >> 12;
    int b    = gw & (B - 1);
    int base, n;
    if (head == 0)      { base = 0;       n = NC; }
    else if (head == 1) { base = NC;      n = NM; }
    else                { base = NC + NM; n = NF; }
    float lx = g_label_xyz[b * 3 + 0];
    float ly = g_label_xyz[b * 3 + 1];
    float lz = g_label_xyz[b * 3 + 2];
    const float* P = g_part_xyz + (size_t)base * 3;
    float best = -2.0f; int bi = 0x7fffffff;
    for (int i = lane; i < n; i += 32) {
        float d = lx * P[i * 3] + ly * P[i * 3 + 1] + lz * P[i * 3 + 2];
        if (d > best || (d == best && i < bi)) { best = d; bi = i; }
    }
#pragma unroll
    for (int off = 16; off > 0; off >>= 1) {
        float ob = __shfl_down_sync(0xffffffffu, best, off);
        int   oi = __shfl_down_sync(0xffffffffu, bi,   off);
        if (ob > best || (ob == best && oi < bi)) { best = ob; bi = oi; }
    }
    if (lane == 0) g_label_idx[head * B + b] = bi;
}

// ============================================================
// Kernel: convert features -> bf16 hi/lo, vectorized float4 -> uint2
// ============================================================
__global__ void k_convA(const float4* __restrict__ A)
{
    int t = blockIdx.x * blockDim.x + threadIdx.x;
    if (t >= (B * D) / 4) return;
    float4 v = A[t];
    __nv_bfloat16 h0 = __float2bfloat16(v.x);
    __nv_bfloat16 h1 = __float2bfloat16(v.y);
    __nv_bfloat16 h2 = __float2bfloat16(v.z);
    __nv_bfloat16 h3 = __float2bfloat16(v.w);
    __nv_bfloat16 l0 = __float2bfloat16(v.x - __bfloat162float(h0));
    __nv_bfloat16 l1 = __float2bfloat16(v.y - __bfloat162float(h1));
    __nv_bfloat16 l2 = __float2bfloat16(v.z - __bfloat162float(h2));
    __nv_bfloat16 l3 = __float2bfloat16(v.w - __bfloat162float(h3));
    uint2 hp, lp;
    hp.x = ((uint32_t)__bfloat16_as_ushort(h1) << 16) | __bfloat16_as_ushort(h0);
    hp.y = ((uint32_t)__bfloat16_as_ushort(h3) << 16) | __bfloat16_as_ushort(h2);
    lp.x = ((uint32_t)__bfloat16_as_ushort(l1) << 16) | __bfloat16_as_ushort(l0);
    lp.y = ((uint32_t)__bfloat16_as_ushort(l3) << 16) | __bfloat16_as_ushort(l2);
    ((uint2*)g_A_hi)[t] = hp;
    ((uint2*)g_A_lo)[t] = lp;
}

// ============================================================
// Kernel: fused transpose+convert for ALL heads:
// W [D][N] -> Wt [NPTOT][D] bf16 hi/lo (zero pad)
// ============================================================
__global__ void k_convW(const float* __restrict__ cw,
                        const float* __restrict__ mw,
                        const float* __restrict__ fw)
{
    __shared__ float t[32][33];
    int k0 = blockIdx.x * 32;
    int ng0 = blockIdx.y * 32;
    const float* W; int N, sec;
    if (ng0 < SEC_M)      { W = cw; N = NC; sec = SEC_C; }
    else if (ng0 < SEC_F) { W = mw; N = NM; sec = SEC_M; }
    else                  { W = fw; N = NF; sec = SEC_F; }
    int n0 = ng0 - sec;
#pragma unroll
    for (int j = 0; j < 32; j += 8) {
        int k = k0 + threadIdx.y + j;
        int n = n0 + threadIdx.x;
        t[threadIdx.y + j][threadIdx.x] = (n < N) ? W[(size_t)k * N + n] : 0.f;
    }
    __syncthreads();
#pragma unroll
    for (int j = 0; j < 32; j += 8) {
        int n = ng0 + threadIdx.y + j;
        int k = k0 + threadIdx.x;
        float v = t[threadIdx.x][threadIdx.y + j];
        __nv_bfloat16 h = __float2bfloat16(v);
        __nv_bfloat16 l = __float2bfloat16(v - __bfloat162float(h));
        size_t o = (size_t)n * D + k;
        g_Wt_hi[o] = h;
        g_Wt_lo[o] = l;
    }
}

// ============================================================
// Merged-pass bf16x3 GEMM: per K-chunk compute AhBh + AhBl + AlBh.
// 128x256 tile, warp tile 64x64, 256 threads, 2-stage pipe.
// 1-D grid + 32x13 supertile rasterization for L2/DRAM reuse.
// In-epilogue per-sub-strip LSE partials.
// ============================================================
#define BM 128
#define BN 256
#define BK 64
#define ST_AH 0
#define ST_AL 16384
#define ST_BH 32768
#define ST_BL 65536
#define STAGE_BYTES 98304
#define GEMM_SMEM (2 * STAGE_BYTES)
#define NKC (D / BK)              // 28
#define GRID_M (B / BM)           // 32
#define GRID_N NSTRIP             // 91 = 7 * 13
#define SUPER_N 13

__global__ __launch_bounds__(256, 1)
void k_mmagemm(const float* __restrict__ cb, const float* __restrict__ mb,
               const float* __restrict__ fb)
{
    extern __shared__ __align__(1024) char smem[];
    uint32_t sb = smem_to_u32(smem);
    const int tid  = threadIdx.x;
    const int wid  = tid >> 5;
    const int lane = tid & 31;
    const int wm   = wid >> 2;     // 0..1
    const int wn   = wid & 3;      // 0..3

    // supertile rasterization: 32 m x 13 n per supertile
    const int gid = blockIdx.x;
    const int sy  = gid / (GRID_M * SUPER_N);
    const int r   = gid % (GRID_M * SUPER_N);
    const int mx  = r / SUPER_N;
    const int ny  = sy * SUPER_N + (r % SUPER_N);
    const int m0  = mx * BM;
    const int n0  = ny * BN;

    int N, sec; size_t outOff; const float* bias;
    if (n0 < SEC_M)      { N = NC; sec = SEC_C; outOff = OFF_C; bias = cb; }
    else if (n0 < SEC_F) { N = NM; sec = SEC_M; outOff = OFF_M; bias = mb; }
    else                 { N = NF; sec = SEC_F; outOff = OFF_F; bias = fb; }
    const int nloc0 = n0 - sec;

    // ---- cp.async addressing: A 4 segs/thread, B 8 segs/thread ----
    uint32_t aSw[4], aGo[4];
#pragma unroll
    for (int i = 0; i < 4; i++) {
        int idx = tid + i * 256;              // 0..1023
        int row = idx >> 3, seg = idx & 7;
        aSw[i] = (uint32_t)(row * 128 + ((seg * 16) ^ ((row & 7) << 4)));
        aGo[i] = (uint32_t)((row * D + seg * 8) * 2);     // byte offset
    }
    uint32_t bSw[8], bGo[8];
#pragma unroll
    for (int i = 0; i < 8; i++) {
        int idx = tid + i * 256;              // 0..2047
        int row = idx >> 3, seg = idx & 7;
        bSw[i] = (uint32_t)(row * 128 + ((seg * 16) ^ ((row & 7) << 4)));
        bGo[i] = (uint32_t)((row * D + seg * 8) * 2);
    }
    const char* Ahp = (const char*)(g_A_hi  + (size_t)m0 * D);
    const char* Alp = (const char*)(g_A_lo  + (size_t)m0 * D);
    const char* Bhp = (const char*)(g_Wt_hi + (size_t)n0 * D);
    const char* Blp = (const char*)(g_Wt_lo + (size_t)n0 * D);

    // ---- ldsm per-lane addressing ----
    uint32_t aTerm[4], aXor[4];
#pragma unroll
    for (int mt = 0; mt < 4; mt++) {
        int row = wm * 64 + mt * 16 + (lane & 7) + ((lane >> 3) & 1) * 8;
        aTerm[mt] = (uint32_t)(row * 128);
        aXor[mt]  = (uint32_t)((row & 7) << 4);
    }
    const uint32_t aCSel = ((lane >> 4) & 1) * 16;
    uint32_t bTerm[4], bXor[4];
#pragma unroll
    for (int np = 0; np < 4; np++) {
        int row = wn * 64 + np * 16 + (lane & 7) + ((lane >> 4) & 1) * 8;
        bTerm[np] = (uint32_t)(row * 128);
        bXor[np]  = (uint32_t)((row & 7) << 4);
    }
    const uint32_t bCSel = ((lane >> 3) & 1) * 16;

    float acc[4][8][4];
#pragma unroll
    for (int i = 0; i < 4; i++)
#pragma unroll
        for (int j = 0; j < 8; j++)
#pragma unroll
            for (int k = 0; k < 4; k++) acc[i][j][k] = 0.f;

#define ISSUE(c) do { \
        int _c = (c); \
        uint32_t kb2 = (uint32_t)(_c * BK * 2); \
        uint32_t st = sb + (uint32_t)(_c & 1) * STAGE_BYTES; \
        _Pragma("unroll") \
        for (int i = 0; i < 4; i++) { \
            CP_ASYNC16(st + ST_AH + aSw[i], Ahp + kb2 + aGo[i]); \
            CP_ASYNC16(st + ST_AL + aSw[i], Alp + kb2 + aGo[i]); \
        } \
        _Pragma("unroll") \
        for (int i = 0; i < 8; i++) { \
            CP_ASYNC16(st + ST_BH + bSw[i], Bhp + kb2 + bGo[i]); \
            CP_ASYNC16(st + ST_BL + bSw[i], Blp + kb2 + bGo[i]); \
        } \
        asm volatile("cp.async.commit_group;" ::: "memory"); \
    } while (0)

    ISSUE(0);
    ISSUE(1);

    for (int c = 0; c < NKC; c++) {
        if (c + 1 < NKC) asm volatile("cp.async.wait_group 1;" ::: "memory");
        else             asm volatile("cp.async.wait_group 0;" ::: "memory");
        __syncthreads();
        uint32_t st = sb + (uint32_t)(c & 1) * STAGE_BYTES;
#pragma unroll
        for (int ks = 0; ks < 4; ks++) {
            const uint32_t kb = (uint32_t)(ks * 32);
            uint32_t a[4][4], bh[4][4], bl[4][4];
#pragma unroll
            for (int mt = 0; mt < 4; mt++)
                ldsm_x4(a[mt], st + ST_AH + aTerm[mt] + ((kb + aCSel) ^ aXor[mt]));
#pragma unroll
            for (int np = 0; np < 4; np++)
                ldsm_x4(bh[np], st + ST_BH + bTerm[np] + ((kb + bCSel) ^ bXor[np]));
#pragma unroll
            for (int np = 0; np < 4; np++)
                ldsm_x4(bl[np], st + ST_BL + bTerm[np] + ((kb + bCSel) ^ bXor[np]));
            // Ah * Bh
#pragma unroll
            for (int mt = 0; mt < 4; mt++)
#pragma unroll
                for (int nt = 0; nt < 8; nt++)
                    mma_bf16(acc[mt][nt], a[mt], &bh[nt >> 1][(nt & 1) * 2]);
            // Ah * Bl
#pragma unroll
            for (int mt = 0; mt < 4; mt++)
#pragma unroll
                for (int nt = 0; nt < 8; nt++)
                    mma_bf16(acc[mt][nt], a[mt], &bl[nt >> 1][(nt & 1) * 2]);
            // Al * Bh (reload a-frags from Al region)
#pragma unroll
            for (int mt = 0; mt < 4; mt++)
                ldsm_x4(a[mt], st + ST_AL + aTerm[mt] + ((kb + aCSel) ^ aXor[mt]));
#pragma unroll
            for (int mt = 0; mt < 4; mt++)
#pragma unroll
                for (int nt = 0; nt < 8; nt++)
                    mma_bf16(acc[mt][nt], a[mt], &bh[nt >> 1][(nt & 1) * 2]);
        }
        __syncthreads();
        if (c + 2 < NKC) ISSUE(c + 2);
    }
#undef ISSUE

    // ---- epilogue: bias + store logits + per-sub-strip LSE partials ----
    float* out = g_logits + outOff;
    const int sub = ny * 4 + wn;
    const int rbase = m0 + wm * 64 + (lane >> 2);
    const int cb0 = nloc0 + wn * 64 + (lane & 3) * 2;
#pragma unroll
    for (int mt = 0; mt < 4; mt++) {
        int r0 = rbase + mt * 16;
        float v0[16], v1[16];
#pragma unroll
        for (int nt = 0; nt < 8; nt++) {
            int col = cb0 + nt * 8;
            bool ok = (col < N);
            float bx = 0.f, by = 0.f;
            if (ok) { bx = bias[col]; by = bias[col + 1]; }
            float a0 = acc[mt][nt][0] + bx;
            float a1 = acc[mt][nt][1] + by;
            float a2 = acc[mt][nt][2] + bx;
            float a3 = acc[mt][nt][3] + by;
            if (ok) {
                float2 w0 = { a0, a1 }, w1 = { a2, a3 };
                *(float2*)&out[(size_t)r0 * N + col]       = w0;
                *(float2*)&out[(size_t)(r0 + 8) * N + col] = w1;
            }
            v0[nt * 2 + 0] = ok ? a0 : -1e30f;
            v0[nt * 2 + 1] = ok ? a1 : -1e30f;
            v1[nt * 2 + 0] = ok ? a2 : -1e30f;
            v1[nt * 2 + 1] = ok ? a3 : -1e30f;
        }
        float m0v = v0[0], m1v = v1[0];
#pragma unroll
        for (int j = 1; j < 16; j++) { m0v = fmaxf(m0v, v0[j]); m1v = fmaxf(m1v, v1[j]); }
#pragma unroll
        for (int o = 1; o <= 2; o <<= 1) {
            m0v = fmaxf(m0v, __shfl_xor_sync(0xffffffffu, m0v, o));
            m1v = fmaxf(m1v, __shfl_xor_sync(0xffffffffu, m1v, o));
        }
        float s0 = 0.f, s1 = 0.f;
#pragma unroll
        for (int j = 0; j < 16; j++) {
            s0 += __expf(v0[j] - m0v);
            s1 += __expf(v1[j] - m1v);
        }
#pragma unroll
        for (int o = 1; o <= 2; o <<= 1) {
            s0 += __shfl_xor_sync(0xffffffffu, s0, o);
            s1 += __shfl_xor_sync(0xffffffffu, s1, o);
        }
        if ((lane & 3) == 0) {
            g_pm[(size_t)sub * B + r0]     = m0v;
            g_ps[(size_t)sub * B + r0]     = s0;
            g_pm[(size_t)sub * B + r0 + 8] = m1v;
            g_ps[(size_t)sub * B + r0 + 8] = s1;
        }
    }
}

// ============================================================
// Tail (512 threads): per row b — combine LSE partials, NLL,
// hierarchical argmax via t[m]=Mv[m]+sC[mp[m]], acc bins.
// ============================================================
#define TAIL_SMEM ((NC + NM) * 4)
#define TAIL_T 512

__global__ __launch_bounds__(TAIL_T)
void k_tail(const float* __restrict__ labels,
            const float* __restrict__ fpart,
            const int*   __restrict__ fparents,
            const int*   __restrict__ mparents)
{
    extern __shared__ float sh[];
    float* sC = sh;          // NC
    float* tM = sh + NC;     // NM
    __shared__ float lseS[3];
    __shared__ float rf[16];
    __shared__ int   ri[16];

    int b = blockIdx.x, tid = threadIdx.x;
    int lane = tid & 31, wid = tid >> 5;
    const float* Cv = g_logits + OFF_C + (size_t)b * NC;
    const float* Mv = g_logits + OFF_M + (size_t)b * NM;
    const float* Fv = g_logits + OFF_F + (size_t)b * NF;

    for (int i = tid; i < NC; i += TAIL_T) sC[i] = Cv[i];

    // warps 0..2: combine per-sub-strip LSE partials for head wid (2-pass)
    if (wid < 3) {
        int base = (wid == 0) ? SUB_C0 : (wid == 1) ? SUB_M0 : SUB_F0;
        int cnt  = (wid == 0) ? SUB_CN : (wid == 1) ? SUB_MN : SUB_FN;
        float m = -3.402823466e38f;
        for (int i = lane; i < cnt; i += 32)
            m = fmaxf(m, g_pm[(size_t)(base + i) * B + b]);
#pragma unroll
        for (int o = 16; o > 0; o >>= 1)
            m = fmaxf(m, __shfl_xor_sync(0xffffffffu, m, o));
        float s = 0.f;
        for (int i = lane; i < cnt; i += 32)
            s += g_ps[(size_t)(base + i) * B + b] *
                 __expf(g_pm[(size_t)(base + i) * B + b] - m);
#pragma unroll
        for (int o = 16; o > 0; o >>= 1)
            s += __shfl_xor_sync(0xffffffffu, s, o);
        if (lane == 0) lseS[wid] = m + logf(s);
    }
    __syncthreads();

    // t[m] = Mv[m] + sC[mparents[m]]
    for (int i = tid; i < NM; i += TAIL_T) tM[i] = Mv[i] + sC[mparents[i]];
    __syncthreads();

    // hierarchical argmax over fine classes
    float best = -3.402823466e38f; int bi = 0x7fffffff;
    for (int f = tid; f < NF; f += TAIL_T) {
        float sc = Fv[f] + tM[fparents[f]];
        if (sc > best) { best = sc; bi = f; }
    }
#pragma unroll
    for (int o = 16; o > 0; o >>= 1) {
        float ob = __shfl_xor_sync(0xffffffffu, best, o);
        int   oi = __shfl_xor_sync(0xffffffffu, bi,   o);
        if (ob > best || (ob == best && oi < bi)) { best = ob; bi = oi; }
    }
    if (lane == 0) { rf[wid] = best; ri[wid] = bi; }
    __syncthreads();

    if (tid == 0) {
        float bb = rf[0]; int pp = ri[0];
#pragma unroll
        for (int j = 1; j < 16; j++) {
            if (rf[j] > bb || (rf[j] == bb && ri[j] < pp)) { bb = rf[j]; pp = ri[j]; }
        }
        int liC = g_label_idx[b];
        int liM = g_label_idx[B + b];
        int liF = g_label_idx[2 * B + b];
        g_nll[b] = (lseS[0] - sC[liC]) + (lseS[1] - Mv[liM]) + (lseS[2] - Fv[liF]);

        const float RADF = 0.017453292519943295f;
        float lat1 = labels[b * 2]      * RADF;
        float lon1 = labels[b * 2 + 1]  * RADF;
        float lat2 = fpart[pp * 2]      * RADF;
        float lon2 = fpart[pp * 2 + 1]  * RADF;
        float sdlat = sinf((lat2 - lat1) * 0.5f);
        float sdlon = sinf((lon2 - lon1) * 0.5f);
        float a = sdlat * sdlat + cosf(lat1) * cosf(lat2) * sdlon * sdlon;
        a = fminf(fmaxf(a, 0.f), 1.f);
        float d = 2.0f * 6371.0f * asinf(sqrtf(a));
        if (d <= 1.0f)    atomicAdd(&g_counts[0], 1);
        if (d <= 25.0f)   atomicAdd(&g_counts[1], 1);
        if (d <= 200.0f)  atomicAdd(&g_counts[2], 1);
        if (d <= 750.0f)  atomicAdd(&g_counts[3], 1);
        if (d <= 2500.0f) atomicAdd(&g_counts[4], 1);
    }
}

// ============================================================
// Final deterministic reduction -> out[0]=loss, out[1..5]=acc
// ============================================================
__global__ void k_finalize(float* __restrict__ out)
{
    __shared__ float red[256];
    int tid = threadIdx.x;
    float s = 0.f;
    for (int i = tid; i < B; i += 256) s += g_nll[i];
    red[tid] = s; __syncthreads();
    for (int st = 128; st > 0; st >>= 1) {
        if (tid < st) red[tid] += red[tid + st];
        __syncthreads();
    }
    if (tid == 0) out[0] = red[0] / (float)B;
    if (tid < 5)  out[1 + tid] = (float)g_counts[tid] / (float)B;
}

// ============================================================
extern "C" void kernel_launch(void* const* d_in, const int* in_sizes, int n_in,
                              void* d_out, int out_size)
{
    const float* features = (const float*)d_in[0];
    const float* labels   = (const float*)d_in[1];
    const float* cpart    = (const float*)d_in[2];
    const float* mpart    = (const float*)d_in[3];
    const float* fpart    = (const float*)d_in[4];
    const int*   mparents = (const int*)d_in[5];
    const int*   fparents = (const int*)d_in[6];
    const float* cw = (const float*)d_in[7];
    const float* cb = (const float*)d_in[8];
    const float* mw = (const float*)d_in[9];
    const float* mb = (const float*)d_in[10];
    const float* fw = (const float*)d_in[11];
    const float* fb = (const float*)d_in[12];
    float* out = (float*)d_out;

    static int s_attr_done = 0;
    if (!s_attr_done) {
        cudaFuncSetAttribute(k_mmagemm, cudaFuncAttributeMaxDynamicSharedMemorySize,
                             GEMM_SMEM);
        cudaFuncSetAttribute(k_tail, cudaFuncAttributeMaxDynamicSharedMemorySize,
                             TAIL_SMEM);
        s_attr_done = 1;
    }

    // order: GEMM is my 4th launch so ncu (-s 5 -c 1) profiles it
    k_convA<<<((B * D) / 4 + 255) / 256, 256>>>((const float4*)features);
    k_convW<<<dim3(D / 32, NPTOT / 32), dim3(32, 8)>>>(cw, mw, fw);
    k_init<<<(NTOT + 255) / 256, 256>>>(labels, cpart, mpart, fpart);

    k_mmagemm<<<GRID_M * GRID_N, 256, GEMM_SMEM>>>(cb, mb, fb);

    k_labelidx<<<(3 * B + 7) / 8, 256>>>();
    k_tail<<<B, TAIL_T, TAIL_SMEM>>>(labels, fpart, fparents, mparents);
    k_finalize<<<1, 256>>>(out);
}